// round 11
// baseline (speedup 1.0000x reference)
#include <cuda_runtime.h>
#include <cuda_bf16.h>
#include <math.h>

// ---------------------------------------------------------------------------
// DKVMN: B=64, L=200, D=128, M=50, FIX=512. Rows = 12800.
//   kv_kernel (z=0): k = k_emb[q]@W1+b1        (z=1): v = v_emb[q+1e4r]@W2+b2
//   wsoftmax : w = softmax(k@Mk^T)  (compact pitch-50)
//   ea_kernel (z=0): e = sigmoid(v@We+be)      (z=1): a = tanh(v@Wa+ba)
//   scan (time-parallel, 8 chunks of 25):
//     P1: per-chunk composed affine (alpha, beta) per (m,d)   [2048 CTAs]
//     P2: sequential 8-step combine -> chunk-entry states
//     P3: per-chunk replay from true entry state -> reads     [2048 CTAs]
//   head : p = sigmoid(tanh([reads|k]@Wf+bf)@Wp+bp)
// ---------------------------------------------------------------------------

#define NROWS 12800
#define NCHUNK 8
#define CLEN 25

__device__ float g_k[NROWS * 128];
__device__ float g_v[NROWS * 128];
__device__ float g_e[NROWS * 128];
__device__ float g_a[NROWS * 128];
__device__ float g_reads[NROWS * 128];
__device__ float g_w[NROWS * 50];                     // compact pitch 50
__device__ float g_alpha[64 * NCHUNK * 50 * 128];     // 13.1 MB
__device__ float g_beta [64 * NCHUNK * 50 * 128];
__device__ float g_minit[64 * NCHUNK * 50 * 128];

__device__ __forceinline__ float fast_tanh(float x) {
    float y;
    asm("tanh.approx.f32 %0, %1;" : "=f"(y) : "f"(x));
    return y;
}
__device__ __forceinline__ float fast_sig(float x) {
    return 0.5f * fast_tanh(0.5f * x) + 0.5f;
}

// ---------------------------------------------------------------------------
// Core 64x64 mainloop (device function). aptr[u]: row base pointers.
// ---------------------------------------------------------------------------
template <int NT>
__device__ __forceinline__ void mm_core(
    const float* const (&aptr)[4], const float* __restrict__ Wb,
    float (&acc)[8][8], float (*As)[16][68], float (*Bs)[16][68],
    int t, int c4, int r0)
{
    float4 ar[4], br[4];
    auto ldA = [&](int kt) {
#pragma unroll
        for (int u = 0; u < 4; ++u)
            ar[u] = *reinterpret_cast<const float4*>(aptr[u] + kt * 16 + c4 * 4);
    };
    auto ldB = [&](int kt) {
#pragma unroll
        for (int u = 0; u < 4; ++u) {
            int e = t + u * 64;
            int rr = e >> 4, cb = e & 15;
            br[u] = *reinterpret_cast<const float4*>(Wb + (size_t)(kt * 16 + rr) * 128 + cb * 4);
        }
    };
    auto stAB = [&](int buf) {
#pragma unroll
        for (int u = 0; u < 4; ++u) {
            int row = r0 + u * 16;
            As[buf][c4 * 4 + 0][row] = ar[u].x;
            As[buf][c4 * 4 + 1][row] = ar[u].y;
            As[buf][c4 * 4 + 2][row] = ar[u].z;
            As[buf][c4 * 4 + 3][row] = ar[u].w;
        }
#pragma unroll
        for (int u = 0; u < 4; ++u) {
            int e = t + u * 64;
            int rr = e >> 4, cb = e & 15;
            *reinterpret_cast<float4*>(&Bs[buf][rr][cb * 4]) = br[u];
        }
    };

    const int cx = t & 7, ry = t >> 3;

    ldA(0); ldB(0); stAB(0);
    __syncthreads();

#pragma unroll 1
    for (int kt = 0; kt < NT; ++kt) {
        const int cur = kt & 1, nxt = cur ^ 1;
        if (kt + 1 < NT) { ldA(kt + 1); ldB(kt + 1); }
#pragma unroll
        for (int kk = 0; kk < 16; ++kk) {
            float4 a0 = *reinterpret_cast<const float4*>(&As[cur][kk][ry * 8]);
            float4 a1 = *reinterpret_cast<const float4*>(&As[cur][kk][ry * 8 + 4]);
            float4 b0 = *reinterpret_cast<const float4*>(&Bs[cur][kk][cx * 8]);
            float4 b1 = *reinterpret_cast<const float4*>(&Bs[cur][kk][cx * 8 + 4]);
            float aa[8] = {a0.x, a0.y, a0.z, a0.w, a1.x, a1.y, a1.z, a1.w};
            float bb[8] = {b0.x, b0.y, b0.z, b0.w, b1.x, b1.y, b1.z, b1.w};
#pragma unroll
            for (int i = 0; i < 8; ++i)
#pragma unroll
                for (int j = 0; j < 8; ++j)
                    acc[i][j] = fmaf(aa[i], bb[j], acc[i][j]);
        }
        if (kt + 1 < NT) stAB(nxt);
        __syncthreads();
    }
}

// ---------------------------------------------------------------------------
// kv_kernel: grid (2, 200, 2). z=0: k path; z=1: v path. K=512 gather GEMM.
// ---------------------------------------------------------------------------
__global__ __launch_bounds__(64) void kv_kernel(
    const float* __restrict__ k_emb, const float* __restrict__ v_emb,
    const int* __restrict__ qi, const int* __restrict__ ri,
    const float* __restrict__ W1, const float* __restrict__ b1,
    const float* __restrict__ W2, const float* __restrict__ b2,
    float* __restrict__ gk, float* __restrict__ gv)
{
    __shared__ float As[2][16][68];
    __shared__ float Bs[2][16][68];

    const int t  = threadIdx.x;
    const int nb = blockIdx.x;
    const int mb = blockIdx.y;
    const int z  = blockIdx.z;
    const int cx = t & 7, ry = t >> 3;
    const int c4 = t & 3, r0 = t >> 2;

    const float* emb  = z ? v_emb : k_emb;
    const float* W    = z ? W2 : W1;
    const float* bias = z ? b2 : b1;
    float*       C    = z ? gv : gk;

    const float* aptr[4];
#pragma unroll
    for (int u = 0; u < 4; ++u) {
        int rr = mb * 64 + r0 + u * 16;
        size_t arow = (size_t)qi[rr];
        if (z) arow += (size_t)10000 * (size_t)ri[rr];
        aptr[u] = emb + arow * 512;
    }
    const float* Wb = W + nb * 64;

    float acc[8][8];
#pragma unroll
    for (int i = 0; i < 8; i++)
#pragma unroll
        for (int j = 0; j < 8; j++) acc[i][j] = 0.f;

    mm_core<32>(aptr, Wb, acc, As, Bs, t, c4, r0);

#pragma unroll
    for (int i = 0; i < 8; ++i) {
        size_t row = (size_t)(mb * 64 + ry * 8 + i);
        float o[8];
#pragma unroll
        for (int j = 0; j < 8; ++j)
            o[j] = acc[i][j] + bias[nb * 64 + cx * 8 + j];
        float* dst = C + row * 128 + nb * 64 + cx * 8;
        *reinterpret_cast<float4*>(dst)     = make_float4(o[0], o[1], o[2], o[3]);
        *reinterpret_cast<float4*>(dst + 4) = make_float4(o[4], o[5], o[6], o[7]);
    }
}

// ---------------------------------------------------------------------------
// ea_kernel: grid (2, 200, 2). z=0: e = sigmoid(v@We+be); z=1: a = tanh(v@Wa+ba)
// ---------------------------------------------------------------------------
__global__ __launch_bounds__(64) void ea_kernel(
    const float* __restrict__ V,
    const float* __restrict__ We, const float* __restrict__ be,
    const float* __restrict__ Wa, const float* __restrict__ ba,
    float* __restrict__ ge, float* __restrict__ ga)
{
    __shared__ float As[2][16][68];
    __shared__ float Bs[2][16][68];

    const int t  = threadIdx.x;
    const int nb = blockIdx.x;
    const int mb = blockIdx.y;
    const int z  = blockIdx.z;
    const int cx = t & 7, ry = t >> 3;
    const int c4 = t & 3, r0 = t >> 2;

    const float* W    = z ? Wa : We;
    const float* bias = z ? ba : be;
    float*       C    = z ? ga : ge;

    const float* aptr[4];
#pragma unroll
    for (int u = 0; u < 4; ++u) {
        int rr = mb * 64 + r0 + u * 16;
        aptr[u] = V + (size_t)rr * 128;
    }
    const float* Wb = W + nb * 64;

    float acc[8][8];
#pragma unroll
    for (int i = 0; i < 8; i++)
#pragma unroll
        for (int j = 0; j < 8; j++) acc[i][j] = 0.f;

    mm_core<8>(aptr, Wb, acc, As, Bs, t, c4, r0);

#pragma unroll
    for (int i = 0; i < 8; ++i) {
        size_t row = (size_t)(mb * 64 + ry * 8 + i);
        float o[8];
#pragma unroll
        for (int j = 0; j < 8; ++j) {
            float vv = acc[i][j] + bias[nb * 64 + cx * 8 + j];
            o[j] = z ? fast_tanh(vv) : fast_sig(vv);
        }
        float* dst = C + row * 128 + nb * 64 + cx * 8;
        *reinterpret_cast<float4*>(dst)     = make_float4(o[0], o[1], o[2], o[3]);
        *reinterpret_cast<float4*>(dst + 4) = make_float4(o[4], o[5], o[6], o[7]);
    }
}

// ---------------------------------------------------------------------------
// head: 64x128 tile, 128 threads, 8x8 per thread, K=256 ([reads|k] concat).
// ---------------------------------------------------------------------------
__global__ __launch_bounds__(128) void head_kernel(
    const float* __restrict__ reads, const float* __restrict__ k,
    const float* __restrict__ Wf, const float* __restrict__ bf,
    const float* __restrict__ Wp, const float* __restrict__ bp,
    float* __restrict__ out)
{
    __shared__ float As[2][16][68];
    __shared__ float Bs[2][16][132];
    __shared__ float pbuf[64][17];

    const int t  = threadIdx.x;
    const int mb = blockIdx.x;
    const int cx = t & 15;
    const int ry = t >> 4;
    const int lrow = t >> 1;
    const int c4b  = (t & 1) * 2;

    const float* aR = reads + (size_t)(mb * 64 + lrow) * 128;
    const float* aK = k     + (size_t)(mb * 64 + lrow) * 128;

    float4 ar[2], br[4];
    auto ldA = [&](int kt) {
#pragma unroll
        for (int u = 0; u < 2; ++u) {
            const float* base = (kt < 8) ? (aR + kt * 16) : (aK + (kt - 8) * 16);
            ar[u] = *reinterpret_cast<const float4*>(base + (c4b + u) * 4);
        }
    };
    auto ldB = [&](int kt) {
#pragma unroll
        for (int u = 0; u < 4; ++u) {
            int e = t + u * 128;
            int rr = e >> 5, cb = e & 31;
            br[u] = *reinterpret_cast<const float4*>(Wf + (size_t)(kt * 16 + rr) * 128 + cb * 4);
        }
    };
    auto stAB = [&](int buf) {
#pragma unroll
        for (int u = 0; u < 2; ++u) {
            int kkb = (c4b + u) * 4;
            As[buf][kkb + 0][lrow] = ar[u].x;
            As[buf][kkb + 1][lrow] = ar[u].y;
            As[buf][kkb + 2][lrow] = ar[u].z;
            As[buf][kkb + 3][lrow] = ar[u].w;
        }
#pragma unroll
        for (int u = 0; u < 4; ++u) {
            int e = t + u * 128;
            int rr = e >> 5, cb = e & 31;
            *reinterpret_cast<float4*>(&Bs[buf][rr][cb * 4]) = br[u];
        }
    };

    float acc[8][8];
#pragma unroll
    for (int i = 0; i < 8; i++)
#pragma unroll
        for (int j = 0; j < 8; j++) acc[i][j] = 0.f;

    ldA(0); ldB(0); stAB(0);
    __syncthreads();

#pragma unroll 1
    for (int kt = 0; kt < 16; ++kt) {
        const int cur = kt & 1, nxt = cur ^ 1;
        if (kt + 1 < 16) { ldA(kt + 1); ldB(kt + 1); }
#pragma unroll
        for (int kk = 0; kk < 16; ++kk) {
            float4 a0 = *reinterpret_cast<const float4*>(&As[cur][kk][ry * 8]);
            float4 a1 = *reinterpret_cast<const float4*>(&As[cur][kk][ry * 8 + 4]);
            float4 b0 = *reinterpret_cast<const float4*>(&Bs[cur][kk][cx * 8]);
            float4 b1 = *reinterpret_cast<const float4*>(&Bs[cur][kk][cx * 8 + 4]);
            float aa[8] = {a0.x, a0.y, a0.z, a0.w, a1.x, a1.y, a1.z, a1.w};
            float bb[8] = {b0.x, b0.y, b0.z, b0.w, b1.x, b1.y, b1.z, b1.w};
#pragma unroll
            for (int i = 0; i < 8; ++i)
#pragma unroll
                for (int j = 0; j < 8; ++j)
                    acc[i][j] = fmaf(aa[i], bb[j], acc[i][j]);
        }
        if (kt + 1 < 16) stAB(nxt);
        __syncthreads();
    }

#pragma unroll
    for (int i = 0; i < 8; ++i) {
        float pac = 0.f;
#pragma unroll
        for (int j = 0; j < 8; ++j) {
            int c = cx * 8 + j;
            float f = fast_tanh(acc[i][j] + bf[c]);
            pac = fmaf(f, Wp[c], pac);
        }
        pbuf[ry * 8 + i][cx] = pac;
    }
    __syncthreads();
    if (t < 64) {
        float s = bp[0];
#pragma unroll
        for (int x = 0; x < 16; ++x) s += pbuf[t][x];
        out[mb * 64 + t] = 1.f / (1.f + __expf(-s));
    }
}

// ---------------------------------------------------------------------------
// w = softmax(k @ Mk^T) : 32 rows/CTA, 128 threads. COMPACT pitch-50 output.
// ---------------------------------------------------------------------------
__global__ __launch_bounds__(128) void wsoftmax_kernel(
    const float* __restrict__ K, const float* __restrict__ Mk,
    float* __restrict__ Wout)
{
    __shared__ float sm_k[32 * 132];
    __shared__ float sm_m[50 * 132];
    float4* kt4 = reinterpret_cast<float4*>(sm_k);
    float4* mk4 = reinterpret_cast<float4*>(sm_m);
    float*  lg  = sm_k;

    const int t  = threadIdx.x;
    const int bi = blockIdx.x;

    for (int e = t; e < 32 * 32; e += 128) {
        int rw = e >> 5, c4 = e & 31;
        kt4[rw * 33 + c4] =
            *reinterpret_cast<const float4*>(K + ((size_t)(bi * 32 + rw)) * 128 + c4 * 4);
    }
    for (int e = t; e < 50 * 32; e += 128) {
        int m = e >> 5, c4 = e & 31;
        mk4[m * 33 + c4] = *reinterpret_cast<const float4*>(Mk + (size_t)m * 128 + c4 * 4);
    }
    __syncthreads();

    const int row = t >> 2;
    const int mg  = t & 3;
    const int m0  = (mg < 2) ? mg * 13 : 26 + (mg - 2) * 12;
    const int cnt = (mg < 2) ? 13 : 12;

    float s[13];
#pragma unroll
    for (int j = 0; j < 13; j++) s[j] = 0.f;

    for (int c4 = 0; c4 < 32; ++c4) {
        float4 kv = kt4[row * 33 + c4];
#pragma unroll
        for (int j = 0; j < 13; j++) {
            if (j < cnt) {
                float4 mv = mk4[(m0 + j) * 33 + c4];
                s[j] = fmaf(kv.x, mv.x, fmaf(kv.y, mv.y,
                        fmaf(kv.z, mv.z, fmaf(kv.w, mv.w, s[j]))));
            }
        }
    }
    __syncthreads();
#pragma unroll
    for (int j = 0; j < 13; j++)
        if (j < cnt) lg[row * 52 + m0 + j] = s[j];
    __syncthreads();

    if (t < 32) {
        float mx = -1e30f;
        for (int m = 0; m < 50; m++) mx = fmaxf(mx, lg[t * 52 + m]);
        float sum = 0.f;
        for (int m = 0; m < 50; m++) sum += __expf(lg[t * 52 + m] - mx);
        float inv = 1.f / sum;
        size_t ob = (size_t)(bi * 32 + t) * 50;
        for (int m = 0; m < 50; m++)
            Wout[ob + m] = __expf(lg[t * 52 + m] - mx) * inv;
    }
}

// ---------------------------------------------------------------------------
// Scan P1: per-chunk composed affine. grid (NCHUNK, 4, 64), 128 threads.
// Lane group-of-4 (mq) owns 12-13 m rows for d = dc*32 + (t>>2).
//   alpha = prod (1 - w e),  beta = beta*(1-we) + w a
// ---------------------------------------------------------------------------
__global__ __launch_bounds__(128) void scan_p1(
    const float* __restrict__ Wm, const float* __restrict__ E,
    const float* __restrict__ Aa,
    float* __restrict__ alpha_o, float* __restrict__ beta_o)
{
    __shared__ float ws[CLEN * 50];

    const int chunk = blockIdx.x;
    const int dc    = blockIdx.y;
    const int b     = blockIdx.z;
    const int t  = threadIdx.x;
    const int mq = t & 3;
    const int d  = dc * 32 + (t >> 2);
    const int m0  = (mq < 2) ? mq * 13 : 26 + (mq - 2) * 12;
    const int cnt = (mq < 2) ? 13 : 12;

    {
        const float2* src = reinterpret_cast<const float2*>(
            Wm + (size_t)b * 10000 + (size_t)chunk * (CLEN * 50));
        float2* dst = reinterpret_cast<float2*>(ws);
        for (int i = t; i < CLEN * 25; i += 128) dst[i] = src[i];
    }
    __syncthreads();

    float al[13], bt[13];
#pragma unroll
    for (int i = 0; i < 13; ++i) { al[i] = 1.f; bt[i] = 0.f; }

    const size_t rowbase = (size_t)b * 200 + (size_t)chunk * CLEN;
    const float* Ep = E  + rowbase * 128 + d;
    const float* Ap = Aa + rowbase * 128 + d;

#pragma unroll 1
    for (int tt = 0; tt < CLEN; ++tt) {
        float ed = Ep[(size_t)tt * 128];
        float ad = Ap[(size_t)tt * 128];
        const float* wrow = ws + tt * 50;
#pragma unroll
        for (int i = 0; i < 13; ++i) {
            if (i < cnt) {
                float wm = wrow[m0 + i];
                float t1 = fmaf(-wm, ed, 1.f);
                al[i] = al[i] * t1;
                bt[i] = fmaf(bt[i], t1, wm * ad);
            }
        }
    }

    const size_t base = ((size_t)(b * NCHUNK + chunk)) * 50;
#pragma unroll
    for (int i = 0; i < 13; ++i) {
        if (i < cnt) {
            size_t off = (base + m0 + i) * 128 + d;
            alpha_o[off] = al[i];
            beta_o[off]  = bt[i];
        }
    }
}

// ---------------------------------------------------------------------------
// Scan P2: sequential combine over chunks. grid (25, 64), 256 threads.
// Thread owns one (m,d); walks 8 chunks: minit[c] = state entering chunk c.
// ---------------------------------------------------------------------------
__global__ __launch_bounds__(256) void scan_p2(
    const float* __restrict__ alpha_i, const float* __restrict__ beta_i,
    const float* __restrict__ Mv0, float* __restrict__ minit)
{
    const int idx = blockIdx.x * 256 + threadIdx.x;   // 0..6399
    const int b   = blockIdx.y;
    const int m   = idx >> 7;
    const int d   = idx & 127;

    float mv = Mv0[m * 128 + d];
#pragma unroll
    for (int c = 0; c < NCHUNK; ++c) {
        size_t off = (((size_t)(b * NCHUNK + c)) * 50 + m) * 128 + d;
        minit[off] = mv;
        mv = fmaf(alpha_i[off], mv, beta_i[off]);
    }
}

// ---------------------------------------------------------------------------
// Scan P3: replay chunk from true entry state, emit reads.
// grid (NCHUNK, 4, 64), 128 threads; same lane layout as P1.
// ---------------------------------------------------------------------------
__global__ __launch_bounds__(128) void scan_p3(
    const float* __restrict__ Wm, const float* __restrict__ E,
    const float* __restrict__ Aa, const float* __restrict__ minit,
    float* __restrict__ R)
{
    __shared__ float ws[CLEN * 50];

    const int chunk = blockIdx.x;
    const int dc    = blockIdx.y;
    const int b     = blockIdx.z;
    const int t  = threadIdx.x;
    const int mq = t & 3;
    const int d  = dc * 32 + (t >> 2);
    const int m0  = (mq < 2) ? mq * 13 : 26 + (mq - 2) * 12;
    const int cnt = (mq < 2) ? 13 : 12;

    {
        const float2* src = reinterpret_cast<const float2*>(
            Wm + (size_t)b * 10000 + (size_t)chunk * (CLEN * 50));
        float2* dst = reinterpret_cast<float2*>(ws);
        for (int i = t; i < CLEN * 25; i += 128) dst[i] = src[i];
    }

    const size_t base = ((size_t)(b * NCHUNK + chunk)) * 50;
    float mv[13];
#pragma unroll
    for (int i = 0; i < 13; ++i)
        if (i < cnt) mv[i] = minit[(base + m0 + i) * 128 + d];
    __syncthreads();

    const size_t rowbase = (size_t)b * 200 + (size_t)chunk * CLEN;
    const float* Ep = E  + rowbase * 128 + d;
    const float* Ap = Aa + rowbase * 128 + d;
    float*       Rp = R  + rowbase * 128 + d;

#pragma unroll 1
    for (int tt = 0; tt < CLEN; ++tt) {
        float ed = Ep[(size_t)tt * 128];
        float ad = Ap[(size_t)tt * 128];
        const float* wrow = ws + tt * 50;
        float ac0 = 0.f, ac1 = 0.f;
#pragma unroll
        for (int i = 0; i < 13; ++i) {
            if (i < cnt) {
                float wm = wrow[m0 + i];
                float mvm = mv[i];
                if (i & 1) ac1 = fmaf(wm, mvm, ac1);
                else       ac0 = fmaf(wm, mvm, ac0);
                mv[i] = fmaf(wm, fmaf(-mvm, ed, ad), mvm);
            }
        }
        float partial = ac0 + ac1;
        partial += __shfl_xor_sync(0xffffffffu, partial, 1);
        partial += __shfl_xor_sync(0xffffffffu, partial, 2);
        if (mq == 0) Rp[(size_t)tt * 128] = partial;
    }
}

// ---------------------------------------------------------------------------
extern "C" void kernel_launch(void* const* d_in, const int* in_sizes, int n_in,
                              void* d_out, int out_size)
{
    const int*   q     = (const int*)d_in[0];
    const int*   r     = (const int*)d_in[1];
    // d_in[2] = diff (unused)
    const float* k_emb = (const float*)d_in[3];
    const float* v_emb = (const float*)d_in[4];
    const float* W1 = (const float*)d_in[5];
    const float* b1 = (const float*)d_in[6];
    const float* W2 = (const float*)d_in[7];
    const float* b2 = (const float*)d_in[8];
    const float* Mk  = (const float*)d_in[9];
    const float* Mv0 = (const float*)d_in[10];
    const float* We = (const float*)d_in[11];
    const float* be = (const float*)d_in[12];
    const float* Wa = (const float*)d_in[13];
    const float* ba = (const float*)d_in[14];
    const float* Wf = (const float*)d_in[15];
    const float* bf = (const float*)d_in[16];
    const float* Wp = (const float*)d_in[17];
    const float* bp = (const float*)d_in[18];
    float* out = (float*)d_out;

    float *pk, *pv, *pe, *pa, *pr, *pw, *pal, *pbt, *pmi;
    cudaGetSymbolAddress((void**)&pk, g_k);
    cudaGetSymbolAddress((void**)&pv, g_v);
    cudaGetSymbolAddress((void**)&pe, g_e);
    cudaGetSymbolAddress((void**)&pa, g_a);
    cudaGetSymbolAddress((void**)&pr, g_reads);
    cudaGetSymbolAddress((void**)&pw, g_w);
    cudaGetSymbolAddress((void**)&pal, g_alpha);
    cudaGetSymbolAddress((void**)&pbt, g_beta);
    cudaGetSymbolAddress((void**)&pmi, g_minit);

    kv_kernel<<<dim3(2, 200, 2), 64>>>(k_emb, v_emb, q, r, W1, b1, W2, b2, pk, pv);
    wsoftmax_kernel<<<400, 128>>>(pk, Mk, pw);
    ea_kernel<<<dim3(2, 200, 2), 64>>>(pv, We, be, Wa, ba, pe, pa);
    scan_p1<<<dim3(NCHUNK, 4, 64), 128>>>(pw, pe, pa, pal, pbt);
    scan_p2<<<dim3(25, 64), 256>>>(pal, pbt, Mv0, pmi);
    scan_p3<<<dim3(NCHUNK, 4, 64), 128>>>(pw, pe, pa, pmi, pr);
    head_kernel<<<200, 128>>>(pr, pk, Wf, bf, Wp, bp, out);
}

// round 13
// speedup vs baseline: 1.1372x; 1.1372x over previous
#include <cuda_runtime.h>
#include <cuda_bf16.h>
#include <math.h>

// ---------------------------------------------------------------------------
// DKVMN: B=64, L=200, D=128, M=50, FIX=512. Rows = 12800.
//   kv_kernel (z=0): k = k_emb[q]@W1+b1        (z=1): v = v_emb[q+1e4r]@W2+b2
//   wsoftmax : w = softmax(k@Mk^T)  (compact pitch-50)
//   ea_kernel (z=0): e = sigmoid(v@We+be)      (z=1): a = tanh(v@Wa+ba)
//   scan : R10 version (single kernel, group-of-4 m split, w in smem)
//   head : p = sigmoid(tanh([reads|k]@Wf+bf)@Wp+bp)
// GEMMs: 128x64 tile, 128 threads (4 warps -> all 4 SMSPs), 8x8/thread.
// ---------------------------------------------------------------------------

#define NROWS 12800

__device__ float g_k[NROWS * 128];
__device__ float g_v[NROWS * 128];
__device__ float g_e[NROWS * 128];
__device__ float g_a[NROWS * 128];
__device__ float g_reads[NROWS * 128];
__device__ float g_w[NROWS * 50];   // compact pitch 50

__device__ __forceinline__ float fast_tanh(float x) {
    float y;
    asm("tanh.approx.f32 %0, %1;" : "=f"(y) : "f"(x));
    return y;
}
__device__ __forceinline__ float fast_sig(float x) {
    return 0.5f * fast_tanh(0.5f * x) + 0.5f;
}

// ---------------------------------------------------------------------------
// Core 128x64 mainloop: 128 threads, 8x8/thread, BK=16, double-buffered.
// aptr[u] (u<4): global row base for rows r0 + u*32 of the 128-row tile.
// ---------------------------------------------------------------------------
template <int NT>
__device__ __forceinline__ void mm_core128(
    const float* const (&aptr)[4], const float* __restrict__ Wb,
    float (&acc)[8][8], float (*As)[16][132], float (*Bs)[16][68],
    int t, int c4, int r0)
{
    float4 ar[4], br[2];
    auto ldA = [&](int kt) {
#pragma unroll
        for (int u = 0; u < 4; ++u)
            ar[u] = *reinterpret_cast<const float4*>(aptr[u] + kt * 16 + c4 * 4);
    };
    auto ldB = [&](int kt) {
#pragma unroll
        for (int u = 0; u < 2; ++u) {
            int e = t + u * 128;
            int rr = e >> 4, cb = e & 15;
            br[u] = *reinterpret_cast<const float4*>(Wb + (size_t)(kt * 16 + rr) * 128 + cb * 4);
        }
    };
    auto stAB = [&](int buf) {
#pragma unroll
        for (int u = 0; u < 4; ++u) {
            int row = r0 + u * 32;
            As[buf][c4 * 4 + 0][row] = ar[u].x;
            As[buf][c4 * 4 + 1][row] = ar[u].y;
            As[buf][c4 * 4 + 2][row] = ar[u].z;
            As[buf][c4 * 4 + 3][row] = ar[u].w;
        }
#pragma unroll
        for (int u = 0; u < 2; ++u) {
            int e = t + u * 128;
            int rr = e >> 4, cb = e & 15;
            *reinterpret_cast<float4*>(&Bs[buf][rr][cb * 4]) = br[u];
        }
    };

    const int cx = t & 7, ry = t >> 3;   // 8 col-groups, 16 row-groups

    ldA(0); ldB(0); stAB(0);
    __syncthreads();

#pragma unroll 1
    for (int kt = 0; kt < NT; ++kt) {
        const int cur = kt & 1, nxt = cur ^ 1;
        if (kt + 1 < NT) { ldA(kt + 1); ldB(kt + 1); }
#pragma unroll
        for (int kk = 0; kk < 16; ++kk) {
            float4 a0 = *reinterpret_cast<const float4*>(&As[cur][kk][ry * 8]);
            float4 a1 = *reinterpret_cast<const float4*>(&As[cur][kk][ry * 8 + 4]);
            float4 b0 = *reinterpret_cast<const float4*>(&Bs[cur][kk][cx * 8]);
            float4 b1 = *reinterpret_cast<const float4*>(&Bs[cur][kk][cx * 8 + 4]);
            float aa[8] = {a0.x, a0.y, a0.z, a0.w, a1.x, a1.y, a1.z, a1.w};
            float bb[8] = {b0.x, b0.y, b0.z, b0.w, b1.x, b1.y, b1.z, b1.w};
#pragma unroll
            for (int i = 0; i < 8; ++i)
#pragma unroll
                for (int j = 0; j < 8; ++j)
                    acc[i][j] = fmaf(aa[i], bb[j], acc[i][j]);
        }
        if (kt + 1 < NT) stAB(nxt);
        __syncthreads();
    }
}

// ---------------------------------------------------------------------------
// kv_kernel: grid (2, 100, 2). z=0: k path; z=1: v path. K=512 gather GEMM.
// ---------------------------------------------------------------------------
__global__ __launch_bounds__(128) void kv_kernel(
    const float* __restrict__ k_emb, const float* __restrict__ v_emb,
    const int* __restrict__ qi, const int* __restrict__ ri,
    const float* __restrict__ W1, const float* __restrict__ b1,
    const float* __restrict__ W2, const float* __restrict__ b2,
    float* __restrict__ gk, float* __restrict__ gv)
{
    __shared__ float As[2][16][132];
    __shared__ float Bs[2][16][68];

    const int t  = threadIdx.x;
    const int nb = blockIdx.x;
    const int mb = blockIdx.y;
    const int z  = blockIdx.z;
    const int cx = t & 7, ry = t >> 3;
    const int c4 = t & 3, r0 = t >> 2;

    const float* emb  = z ? v_emb : k_emb;
    const float* W    = z ? W2 : W1;
    const float* bias = z ? b2 : b1;
    float*       C    = z ? gv : gk;

    const float* aptr[4];
#pragma unroll
    for (int u = 0; u < 4; ++u) {
        int rr = mb * 128 + r0 + u * 32;
        size_t arow = (size_t)qi[rr];
        if (z) arow += (size_t)10000 * (size_t)ri[rr];
        aptr[u] = emb + arow * 512;
    }
    const float* Wb = W + nb * 64;

    float acc[8][8];
#pragma unroll
    for (int i = 0; i < 8; i++)
#pragma unroll
        for (int j = 0; j < 8; j++) acc[i][j] = 0.f;

    mm_core128<32>(aptr, Wb, acc, As, Bs, t, c4, r0);

#pragma unroll
    for (int i = 0; i < 8; ++i) {
        size_t row = (size_t)(mb * 128 + ry * 8 + i);
        float o[8];
#pragma unroll
        for (int j = 0; j < 8; ++j)
            o[j] = acc[i][j] + bias[nb * 64 + cx * 8 + j];
        float* dst = C + row * 128 + nb * 64 + cx * 8;
        *reinterpret_cast<float4*>(dst)     = make_float4(o[0], o[1], o[2], o[3]);
        *reinterpret_cast<float4*>(dst + 4) = make_float4(o[4], o[5], o[6], o[7]);
    }
}

// ---------------------------------------------------------------------------
// ea_kernel: grid (2, 100, 2). z=0: e = sigmoid(v@We+be); z=1: a = tanh(v@Wa+ba)
// ---------------------------------------------------------------------------
__global__ __launch_bounds__(128) void ea_kernel(
    const float* __restrict__ V,
    const float* __restrict__ We, const float* __restrict__ be,
    const float* __restrict__ Wa, const float* __restrict__ ba,
    float* __restrict__ ge, float* __restrict__ ga)
{
    __shared__ float As[2][16][132];
    __shared__ float Bs[2][16][68];

    const int t  = threadIdx.x;
    const int nb = blockIdx.x;
    const int mb = blockIdx.y;
    const int z  = blockIdx.z;
    const int cx = t & 7, ry = t >> 3;
    const int c4 = t & 3, r0 = t >> 2;

    const float* W    = z ? Wa : We;
    const float* bias = z ? ba : be;
    float*       C    = z ? ga : ge;

    const float* aptr[4];
#pragma unroll
    for (int u = 0; u < 4; ++u) {
        int rr = mb * 128 + r0 + u * 32;
        aptr[u] = V + (size_t)rr * 128;
    }
    const float* Wb = W + nb * 64;

    float acc[8][8];
#pragma unroll
    for (int i = 0; i < 8; i++)
#pragma unroll
        for (int j = 0; j < 8; j++) acc[i][j] = 0.f;

    mm_core128<8>(aptr, Wb, acc, As, Bs, t, c4, r0);

#pragma unroll
    for (int i = 0; i < 8; ++i) {
        size_t row = (size_t)(mb * 128 + ry * 8 + i);
        float o[8];
#pragma unroll
        for (int j = 0; j < 8; ++j) {
            float vv = acc[i][j] + bias[nb * 64 + cx * 8 + j];
            o[j] = z ? fast_tanh(vv) : fast_sig(vv);
        }
        float* dst = C + row * 128 + nb * 64 + cx * 8;
        *reinterpret_cast<float4*>(dst)     = make_float4(o[0], o[1], o[2], o[3]);
        *reinterpret_cast<float4*>(dst + 4) = make_float4(o[4], o[5], o[6], o[7]);
    }
}

// ---------------------------------------------------------------------------
// head: 64x128 tile, 128 threads, 8x8 per thread, K=256 ([reads|k] concat).
// ---------------------------------------------------------------------------
__global__ __launch_bounds__(128) void head_kernel(
    const float* __restrict__ reads, const float* __restrict__ k,
    const float* __restrict__ Wf, const float* __restrict__ bf,
    const float* __restrict__ Wp, const float* __restrict__ bp,
    float* __restrict__ out)
{
    __shared__ float As[2][16][68];
    __shared__ float Bs[2][16][132];
    __shared__ float pbuf[64][17];

    const int t  = threadIdx.x;
    const int mb = blockIdx.x;
    const int cx = t & 15;
    const int ry = t >> 4;
    const int lrow = t >> 1;
    const int c4b  = (t & 1) * 2;

    const float* aR = reads + (size_t)(mb * 64 + lrow) * 128;
    const float* aK = k     + (size_t)(mb * 64 + lrow) * 128;

    float4 ar[2], br[4];
    auto ldA = [&](int kt) {
#pragma unroll
        for (int u = 0; u < 2; ++u) {
            const float* base = (kt < 8) ? (aR + kt * 16) : (aK + (kt - 8) * 16);
            ar[u] = *reinterpret_cast<const float4*>(base + (c4b + u) * 4);
        }
    };
    auto ldB = [&](int kt) {
#pragma unroll
        for (int u = 0; u < 4; ++u) {
            int e = t + u * 128;
            int rr = e >> 5, cb = e & 31;
            br[u] = *reinterpret_cast<const float4*>(Wf + (size_t)(kt * 16 + rr) * 128 + cb * 4);
        }
    };
    auto stAB = [&](int buf) {
#pragma unroll
        for (int u = 0; u < 2; ++u) {
            int kkb = (c4b + u) * 4;
            As[buf][kkb + 0][lrow] = ar[u].x;
            As[buf][kkb + 1][lrow] = ar[u].y;
            As[buf][kkb + 2][lrow] = ar[u].z;
            As[buf][kkb + 3][lrow] = ar[u].w;
        }
#pragma unroll
        for (int u = 0; u < 4; ++u) {
            int e = t + u * 128;
            int rr = e >> 5, cb = e & 31;
            *reinterpret_cast<float4*>(&Bs[buf][rr][cb * 4]) = br[u];
        }
    };

    float acc[8][8];
#pragma unroll
    for (int i = 0; i < 8; i++)
#pragma unroll
        for (int j = 0; j < 8; j++) acc[i][j] = 0.f;

    ldA(0); ldB(0); stAB(0);
    __syncthreads();

#pragma unroll 1
    for (int kt = 0; kt < 16; ++kt) {
        const int cur = kt & 1, nxt = cur ^ 1;
        if (kt + 1 < 16) { ldA(kt + 1); ldB(kt + 1); }
#pragma unroll
        for (int kk = 0; kk < 16; ++kk) {
            float4 a0 = *reinterpret_cast<const float4*>(&As[cur][kk][ry * 8]);
            float4 a1 = *reinterpret_cast<const float4*>(&As[cur][kk][ry * 8 + 4]);
            float4 b0 = *reinterpret_cast<const float4*>(&Bs[cur][kk][cx * 8]);
            float4 b1 = *reinterpret_cast<const float4*>(&Bs[cur][kk][cx * 8 + 4]);
            float aa[8] = {a0.x, a0.y, a0.z, a0.w, a1.x, a1.y, a1.z, a1.w};
            float bb[8] = {b0.x, b0.y, b0.z, b0.w, b1.x, b1.y, b1.z, b1.w};
#pragma unroll
            for (int i = 0; i < 8; ++i)
#pragma unroll
                for (int j = 0; j < 8; ++j)
                    acc[i][j] = fmaf(aa[i], bb[j], acc[i][j]);
        }
        if (kt + 1 < 16) stAB(nxt);
        __syncthreads();
    }

#pragma unroll
    for (int i = 0; i < 8; ++i) {
        float pac = 0.f;
#pragma unroll
        for (int j = 0; j < 8; ++j) {
            int c = cx * 8 + j;
            float f = fast_tanh(acc[i][j] + bf[c]);
            pac = fmaf(f, Wp[c], pac);
        }
        pbuf[ry * 8 + i][cx] = pac;
    }
    __syncthreads();
    if (t < 64) {
        float s = bp[0];
#pragma unroll
        for (int x = 0; x < 16; ++x) s += pbuf[t][x];
        out[mb * 64 + t] = 1.f / (1.f + __expf(-s));
    }
}

// ---------------------------------------------------------------------------
// w = softmax(k @ Mk^T) : 32 rows/CTA, 128 threads. COMPACT pitch-50 output.
// ---------------------------------------------------------------------------
__global__ __launch_bounds__(128) void wsoftmax_kernel(
    const float* __restrict__ K, const float* __restrict__ Mk,
    float* __restrict__ Wout)
{
    __shared__ float sm_k[32 * 132];
    __shared__ float sm_m[50 * 132];
    float4* kt4 = reinterpret_cast<float4*>(sm_k);
    float4* mk4 = reinterpret_cast<float4*>(sm_m);
    float*  lg  = sm_k;

    const int t  = threadIdx.x;
    const int bi = blockIdx.x;

    for (int e = t; e < 32 * 32; e += 128) {
        int rw = e >> 5, c4 = e & 31;
        kt4[rw * 33 + c4] =
            *reinterpret_cast<const float4*>(K + ((size_t)(bi * 32 + rw)) * 128 + c4 * 4);
    }
    for (int e = t; e < 50 * 32; e += 128) {
        int m = e >> 5, c4 = e & 31;
        mk4[m * 33 + c4] = *reinterpret_cast<const float4*>(Mk + (size_t)m * 128 + c4 * 4);
    }
    __syncthreads();

    const int row = t >> 2;
    const int mg  = t & 3;
    const int m0  = (mg < 2) ? mg * 13 : 26 + (mg - 2) * 12;
    const int cnt = (mg < 2) ? 13 : 12;

    float s[13];
#pragma unroll
    for (int j = 0; j < 13; j++) s[j] = 0.f;

    for (int c4 = 0; c4 < 32; ++c4) {
        float4 kv = kt4[row * 33 + c4];
#pragma unroll
        for (int j = 0; j < 13; j++) {
            if (j < cnt) {
                float4 mv = mk4[(m0 + j) * 33 + c4];
                s[j] = fmaf(kv.x, mv.x, fmaf(kv.y, mv.y,
                        fmaf(kv.z, mv.z, fmaf(kv.w, mv.w, s[j]))));
            }
        }
    }
    __syncthreads();
#pragma unroll
    for (int j = 0; j < 13; j++)
        if (j < cnt) lg[row * 52 + m0 + j] = s[j];
    __syncthreads();

    if (t < 32) {
        float mx = -1e30f;
        for (int m = 0; m < 50; m++) mx = fmaxf(mx, lg[t * 52 + m]);
        float sum = 0.f;
        for (int m = 0; m < 50; m++) sum += __expf(lg[t * 52 + m] - mx);
        float inv = 1.f / sum;
        size_t ob = (size_t)(bi * 32 + t) * 50;
        for (int m = 0; m < 50; m++)
            Wout[ob + m] = __expf(lg[t * 52 + m] - mx) * inv;
    }
}

// ---------------------------------------------------------------------------
// Scan (R10): grid (4 d-chunks, 64 batches), 128 threads. Lane group-of-4:
// d = dc*32 + (t>>2), mq = t&3 owns 12-13 of the 50 Mv rows in registers.
// w staged in smem (uniform LDS). r_t closed by 2 shfl_xor (off recurrence).
// ---------------------------------------------------------------------------
__global__ __launch_bounds__(128) void scan_kernel(
    const float* __restrict__ Wm, const float* __restrict__ E,
    const float* __restrict__ Aa, const float* __restrict__ Mv0,
    float* __restrict__ R)
{
    __shared__ float ws[200 * 50];    // 40 KB

    const int dc = blockIdx.x;
    const int b  = blockIdx.y;
    const int t  = threadIdx.x;
    const int mq = t & 3;
    const int d  = dc * 32 + (t >> 2);
    const int m0  = (mq < 2) ? mq * 13 : 26 + (mq - 2) * 12;
    const int cnt = (mq < 2) ? 13 : 12;

    {
        const float4* src = reinterpret_cast<const float4*>(Wm + (size_t)b * 10000);
        float4* dst = reinterpret_cast<float4*>(ws);
        for (int i = t; i < 2500; i += 128) dst[i] = src[i];
    }

    float mv[13];
#pragma unroll
    for (int i = 0; i < 13; ++i)
        if (i < cnt) mv[i] = Mv0[(m0 + i) * 128 + d];
    __syncthreads();

    const size_t rowbase = (size_t)b * 200;
    const float* Ep = E  + rowbase * 128 + d;
    const float* Ap = Aa + rowbase * 128 + d;
    float*       Rp = R  + rowbase * 128 + d;

    float ed = Ep[0];
    float ad = Ap[0];

#pragma unroll 2
    for (int tt = 0; tt < 200; ++tt) {
        float en = 0.f, an = 0.f;
        if (tt < 199) {
            en = Ep[(size_t)(tt + 1) * 128];
            an = Ap[(size_t)(tt + 1) * 128];
        }

        const float* wrow = ws + tt * 50;
        float ac0 = 0.f, ac1 = 0.f;
#pragma unroll
        for (int i = 0; i < 13; ++i) {
            if (i < cnt) {
                float wm = wrow[m0 + i];
                float mvm = mv[i];
                if (i & 1) ac1 = fmaf(wm, mvm, ac1);
                else       ac0 = fmaf(wm, mvm, ac0);
                mv[i] = fmaf(wm, fmaf(-mvm, ed, ad), mvm);
            }
        }
        float partial = ac0 + ac1;
        partial += __shfl_xor_sync(0xffffffffu, partial, 1);
        partial += __shfl_xor_sync(0xffffffffu, partial, 2);
        if (mq == 0) Rp[(size_t)tt * 128] = partial;

        ed = en; ad = an;
    }
}

// ---------------------------------------------------------------------------
extern "C" void kernel_launch(void* const* d_in, const int* in_sizes, int n_in,
                              void* d_out, int out_size)
{
    const int*   q     = (const int*)d_in[0];
    const int*   r     = (const int*)d_in[1];
    // d_in[2] = diff (unused)
    const float* k_emb = (const float*)d_in[3];
    const float* v_emb = (const float*)d_in[4];
    const float* W1 = (const float*)d_in[5];
    const float* b1 = (const float*)d_in[6];
    const float* W2 = (const float*)d_in[7];
    const float* b2 = (const float*)d_in[8];
    const float* Mk  = (const float*)d_in[9];
    const float* Mv0 = (const float*)d_in[10];
    const float* We = (const float*)d_in[11];
    const float* be = (const float*)d_in[12];
    const float* Wa = (const float*)d_in[13];
    const float* ba = (const float*)d_in[14];
    const float* Wf = (const float*)d_in[15];
    const float* bf = (const float*)d_in[16];
    const float* Wp = (const float*)d_in[17];
    const float* bp = (const float*)d_in[18];
    float* out = (float*)d_out;

    float *pk, *pv, *pe, *pa, *pr, *pw;
    cudaGetSymbolAddress((void**)&pk, g_k);
    cudaGetSymbolAddress((void**)&pv, g_v);
    cudaGetSymbolAddress((void**)&pe, g_e);
    cudaGetSymbolAddress((void**)&pa, g_a);
    cudaGetSymbolAddress((void**)&pr, g_reads);
    cudaGetSymbolAddress((void**)&pw, g_w);

    kv_kernel<<<dim3(2, 100, 2), 128>>>(k_emb, v_emb, q, r, W1, b1, W2, b2, pk, pv);
    wsoftmax_kernel<<<400, 128>>>(pk, Mk, pw);
    ea_kernel<<<dim3(2, 100, 2), 128>>>(pv, We, be, Wa, ba, pe, pa);
    scan_kernel<<<dim3(4, 64), 128>>>(pw, pe, pa, Mv0, pr);
    head_kernel<<<200, 128>>>(pr, pk, Wf, bf, Wp, bp, out);
}

// round 14
// speedup vs baseline: 1.2047x; 1.0593x over previous
#include <cuda_runtime.h>
#include <cuda_bf16.h>
#include <math.h>

// ---------------------------------------------------------------------------
// DKVMN: B=64, L=200, D=128, M=50, FIX=512. Rows = 12800.
//   kv_kernel (z=0): k = k_emb[q]@W1+b1        (z=1): v = v_emb[q+1e4r]@W2+b2
//   wsoftmax : w = softmax(k@Mk^T)  (compact pitch-50)
//   ea_kernel (z=0): e = sigmoid(v@We+be)      (z=1): a = tanh(v@Wa+ba)
//   scan : group-of-4 m split, w in smem, E/A 8-deep register prefetch.
//   head : p = sigmoid(tanh([reads|k]@Wf+bf)@Wp+bp)
// ---------------------------------------------------------------------------

#define NROWS 12800

__device__ float g_k[NROWS * 128];
__device__ float g_v[NROWS * 128];
__device__ float g_e[NROWS * 128];
__device__ float g_a[NROWS * 128];
__device__ float g_reads[NROWS * 128];
__device__ float g_w[NROWS * 50];   // compact pitch 50

__device__ __forceinline__ float fast_tanh(float x) {
    float y;
    asm("tanh.approx.f32 %0, %1;" : "=f"(y) : "f"(x));
    return y;
}
__device__ __forceinline__ float fast_sig(float x) {
    return 0.5f * fast_tanh(0.5f * x) + 0.5f;
}

// ---------------------------------------------------------------------------
// Core 128x64 mainloop: 128 threads, 8x8/thread, BK=16, double-buffered.
// ---------------------------------------------------------------------------
template <int NT>
__device__ __forceinline__ void mm_core128(
    const float* const (&aptr)[4], const float* __restrict__ Wb,
    float (&acc)[8][8], float (*As)[16][132], float (*Bs)[16][68],
    int t, int c4, int r0)
{
    float4 ar[4], br[2];
    auto ldA = [&](int kt) {
#pragma unroll
        for (int u = 0; u < 4; ++u)
            ar[u] = *reinterpret_cast<const float4*>(aptr[u] + kt * 16 + c4 * 4);
    };
    auto ldB = [&](int kt) {
#pragma unroll
        for (int u = 0; u < 2; ++u) {
            int e = t + u * 128;
            int rr = e >> 4, cb = e & 15;
            br[u] = *reinterpret_cast<const float4*>(Wb + (size_t)(kt * 16 + rr) * 128 + cb * 4);
        }
    };
    auto stAB = [&](int buf) {
#pragma unroll
        for (int u = 0; u < 4; ++u) {
            int row = r0 + u * 32;
            As[buf][c4 * 4 + 0][row] = ar[u].x;
            As[buf][c4 * 4 + 1][row] = ar[u].y;
            As[buf][c4 * 4 + 2][row] = ar[u].z;
            As[buf][c4 * 4 + 3][row] = ar[u].w;
        }
#pragma unroll
        for (int u = 0; u < 2; ++u) {
            int e = t + u * 128;
            int rr = e >> 4, cb = e & 15;
            *reinterpret_cast<float4*>(&Bs[buf][rr][cb * 4]) = br[u];
        }
    };

    const int cx = t & 7, ry = t >> 3;

    ldA(0); ldB(0); stAB(0);
    __syncthreads();

#pragma unroll 1
    for (int kt = 0; kt < NT; ++kt) {
        const int cur = kt & 1, nxt = cur ^ 1;
        if (kt + 1 < NT) { ldA(kt + 1); ldB(kt + 1); }
#pragma unroll
        for (int kk = 0; kk < 16; ++kk) {
            float4 a0 = *reinterpret_cast<const float4*>(&As[cur][kk][ry * 8]);
            float4 a1 = *reinterpret_cast<const float4*>(&As[cur][kk][ry * 8 + 4]);
            float4 b0 = *reinterpret_cast<const float4*>(&Bs[cur][kk][cx * 8]);
            float4 b1 = *reinterpret_cast<const float4*>(&Bs[cur][kk][cx * 8 + 4]);
            float aa[8] = {a0.x, a0.y, a0.z, a0.w, a1.x, a1.y, a1.z, a1.w};
            float bb[8] = {b0.x, b0.y, b0.z, b0.w, b1.x, b1.y, b1.z, b1.w};
#pragma unroll
            for (int i = 0; i < 8; ++i)
#pragma unroll
                for (int j = 0; j < 8; ++j)
                    acc[i][j] = fmaf(aa[i], bb[j], acc[i][j]);
        }
        if (kt + 1 < NT) stAB(nxt);
        __syncthreads();
    }
}

// ---------------------------------------------------------------------------
// kv_kernel: grid (2, 100, 2). z=0: k path; z=1: v path. K=512 gather GEMM.
// ---------------------------------------------------------------------------
__global__ __launch_bounds__(128) void kv_kernel(
    const float* __restrict__ k_emb, const float* __restrict__ v_emb,
    const int* __restrict__ qi, const int* __restrict__ ri,
    const float* __restrict__ W1, const float* __restrict__ b1,
    const float* __restrict__ W2, const float* __restrict__ b2,
    float* __restrict__ gk, float* __restrict__ gv)
{
    __shared__ float As[2][16][132];
    __shared__ float Bs[2][16][68];

    const int t  = threadIdx.x;
    const int nb = blockIdx.x;
    const int mb = blockIdx.y;
    const int z  = blockIdx.z;
    const int cx = t & 7, ry = t >> 3;
    const int c4 = t & 3, r0 = t >> 2;

    const float* emb  = z ? v_emb : k_emb;
    const float* W    = z ? W2 : W1;
    const float* bias = z ? b2 : b1;
    float*       C    = z ? gv : gk;

    const float* aptr[4];
#pragma unroll
    for (int u = 0; u < 4; ++u) {
        int rr = mb * 128 + r0 + u * 32;
        size_t arow = (size_t)qi[rr];
        if (z) arow += (size_t)10000 * (size_t)ri[rr];
        aptr[u] = emb + arow * 512;
    }
    const float* Wb = W + nb * 64;

    float acc[8][8];
#pragma unroll
    for (int i = 0; i < 8; i++)
#pragma unroll
        for (int j = 0; j < 8; j++) acc[i][j] = 0.f;

    mm_core128<32>(aptr, Wb, acc, As, Bs, t, c4, r0);

#pragma unroll
    for (int i = 0; i < 8; ++i) {
        size_t row = (size_t)(mb * 128 + ry * 8 + i);
        float o[8];
#pragma unroll
        for (int j = 0; j < 8; ++j)
            o[j] = acc[i][j] + bias[nb * 64 + cx * 8 + j];
        float* dst = C + row * 128 + nb * 64 + cx * 8;
        *reinterpret_cast<float4*>(dst)     = make_float4(o[0], o[1], o[2], o[3]);
        *reinterpret_cast<float4*>(dst + 4) = make_float4(o[4], o[5], o[6], o[7]);
    }
}

// ---------------------------------------------------------------------------
// ea_kernel: grid (2, 100, 2). z=0: e = sigmoid(v@We+be); z=1: a = tanh(v@Wa+ba)
// ---------------------------------------------------------------------------
__global__ __launch_bounds__(128) void ea_kernel(
    const float* __restrict__ V,
    const float* __restrict__ We, const float* __restrict__ be,
    const float* __restrict__ Wa, const float* __restrict__ ba,
    float* __restrict__ ge, float* __restrict__ ga)
{
    __shared__ float As[2][16][132];
    __shared__ float Bs[2][16][68];

    const int t  = threadIdx.x;
    const int nb = blockIdx.x;
    const int mb = blockIdx.y;
    const int z  = blockIdx.z;
    const int cx = t & 7, ry = t >> 3;
    const int c4 = t & 3, r0 = t >> 2;

    const float* W    = z ? Wa : We;
    const float* bias = z ? ba : be;
    float*       C    = z ? ga : ge;

    const float* aptr[4];
#pragma unroll
    for (int u = 0; u < 4; ++u) {
        int rr = mb * 128 + r0 + u * 32;
        aptr[u] = V + (size_t)rr * 128;
    }
    const float* Wb = W + nb * 64;

    float acc[8][8];
#pragma unroll
    for (int i = 0; i < 8; i++)
#pragma unroll
        for (int j = 0; j < 8; j++) acc[i][j] = 0.f;

    mm_core128<8>(aptr, Wb, acc, As, Bs, t, c4, r0);

#pragma unroll
    for (int i = 0; i < 8; ++i) {
        size_t row = (size_t)(mb * 128 + ry * 8 + i);
        float o[8];
#pragma unroll
        for (int j = 0; j < 8; ++j) {
            float vv = acc[i][j] + bias[nb * 64 + cx * 8 + j];
            o[j] = z ? fast_tanh(vv) : fast_sig(vv);
        }
        float* dst = C + row * 128 + nb * 64 + cx * 8;
        *reinterpret_cast<float4*>(dst)     = make_float4(o[0], o[1], o[2], o[3]);
        *reinterpret_cast<float4*>(dst + 4) = make_float4(o[4], o[5], o[6], o[7]);
    }
}

// ---------------------------------------------------------------------------
// head: 64x128 tile, 128 threads, 8x8 per thread, K=256 ([reads|k] concat).
// ---------------------------------------------------------------------------
__global__ __launch_bounds__(128) void head_kernel(
    const float* __restrict__ reads, const float* __restrict__ k,
    const float* __restrict__ Wf, const float* __restrict__ bf,
    const float* __restrict__ Wp, const float* __restrict__ bp,
    float* __restrict__ out)
{
    __shared__ float As[2][16][68];
    __shared__ float Bs[2][16][132];
    __shared__ float pbuf[64][17];

    const int t  = threadIdx.x;
    const int mb = blockIdx.x;
    const int cx = t & 15;
    const int ry = t >> 4;
    const int lrow = t >> 1;
    const int c4b  = (t & 1) * 2;

    const float* aR = reads + (size_t)(mb * 64 + lrow) * 128;
    const float* aK = k     + (size_t)(mb * 64 + lrow) * 128;

    float4 ar[2], br[4];
    auto ldA = [&](int kt) {
#pragma unroll
        for (int u = 0; u < 2; ++u) {
            const float* base = (kt < 8) ? (aR + kt * 16) : (aK + (kt - 8) * 16);
            ar[u] = *reinterpret_cast<const float4*>(base + (c4b + u) * 4);
        }
    };
    auto ldB = [&](int kt) {
#pragma unroll
        for (int u = 0; u < 4; ++u) {
            int e = t + u * 128;
            int rr = e >> 5, cb = e & 31;
            br[u] = *reinterpret_cast<const float4*>(Wf + (size_t)(kt * 16 + rr) * 128 + cb * 4);
        }
    };
    auto stAB = [&](int buf) {
#pragma unroll
        for (int u = 0; u < 2; ++u) {
            int kkb = (c4b + u) * 4;
            As[buf][kkb + 0][lrow] = ar[u].x;
            As[buf][kkb + 1][lrow] = ar[u].y;
            As[buf][kkb + 2][lrow] = ar[u].z;
            As[buf][kkb + 3][lrow] = ar[u].w;
        }
#pragma unroll
        for (int u = 0; u < 4; ++u) {
            int e = t + u * 128;
            int rr = e >> 5, cb = e & 31;
            *reinterpret_cast<float4*>(&Bs[buf][rr][cb * 4]) = br[u];
        }
    };

    float acc[8][8];
#pragma unroll
    for (int i = 0; i < 8; i++)
#pragma unroll
        for (int j = 0; j < 8; j++) acc[i][j] = 0.f;

    ldA(0); ldB(0); stAB(0);
    __syncthreads();

#pragma unroll 1
    for (int kt = 0; kt < 16; ++kt) {
        const int cur = kt & 1, nxt = cur ^ 1;
        if (kt + 1 < 16) { ldA(kt + 1); ldB(kt + 1); }
#pragma unroll
        for (int kk = 0; kk < 16; ++kk) {
            float4 a0 = *reinterpret_cast<const float4*>(&As[cur][kk][ry * 8]);
            float4 a1 = *reinterpret_cast<const float4*>(&As[cur][kk][ry * 8 + 4]);
            float4 b0 = *reinterpret_cast<const float4*>(&Bs[cur][kk][cx * 8]);
            float4 b1 = *reinterpret_cast<const float4*>(&Bs[cur][kk][cx * 8 + 4]);
            float aa[8] = {a0.x, a0.y, a0.z, a0.w, a1.x, a1.y, a1.z, a1.w};
            float bb[8] = {b0.x, b0.y, b0.z, b0.w, b1.x, b1.y, b1.z, b1.w};
#pragma unroll
            for (int i = 0; i < 8; ++i)
#pragma unroll
                for (int j = 0; j < 8; ++j)
                    acc[i][j] = fmaf(aa[i], bb[j], acc[i][j]);
        }
        if (kt + 1 < 16) stAB(nxt);
        __syncthreads();
    }

#pragma unroll
    for (int i = 0; i < 8; ++i) {
        float pac = 0.f;
#pragma unroll
        for (int j = 0; j < 8; ++j) {
            int c = cx * 8 + j;
            float f = fast_tanh(acc[i][j] + bf[c]);
            pac = fmaf(f, Wp[c], pac);
        }
        pbuf[ry * 8 + i][cx] = pac;
    }
    __syncthreads();
    if (t < 64) {
        float s = bp[0];
#pragma unroll
        for (int x = 0; x < 16; ++x) s += pbuf[t][x];
        out[mb * 64 + t] = 1.f / (1.f + __expf(-s));
    }
}

// ---------------------------------------------------------------------------
// w = softmax(k @ Mk^T) : 32 rows/CTA, 128 threads. COMPACT pitch-50 output.
// ---------------------------------------------------------------------------
__global__ __launch_bounds__(128) void wsoftmax_kernel(
    const float* __restrict__ K, const float* __restrict__ Mk,
    float* __restrict__ Wout)
{
    __shared__ float sm_k[32 * 132];
    __shared__ float sm_m[50 * 132];
    float4* kt4 = reinterpret_cast<float4*>(sm_k);
    float4* mk4 = reinterpret_cast<float4*>(sm_m);
    float*  lg  = sm_k;

    const int t  = threadIdx.x;
    const int bi = blockIdx.x;

    for (int e = t; e < 32 * 32; e += 128) {
        int rw = e >> 5, c4 = e & 31;
        kt4[rw * 33 + c4] =
            *reinterpret_cast<const float4*>(K + ((size_t)(bi * 32 + rw)) * 128 + c4 * 4);
    }
    for (int e = t; e < 50 * 32; e += 128) {
        int m = e >> 5, c4 = e & 31;
        mk4[m * 33 + c4] = *reinterpret_cast<const float4*>(Mk + (size_t)m * 128 + c4 * 4);
    }
    __syncthreads();

    const int row = t >> 2;
    const int mg  = t & 3;
    const int m0  = (mg < 2) ? mg * 13 : 26 + (mg - 2) * 12;
    const int cnt = (mg < 2) ? 13 : 12;

    float s[13];
#pragma unroll
    for (int j = 0; j < 13; j++) s[j] = 0.f;

    for (int c4 = 0; c4 < 32; ++c4) {
        float4 kv = kt4[row * 33 + c4];
#pragma unroll
        for (int j = 0; j < 13; j++) {
            if (j < cnt) {
                float4 mv = mk4[(m0 + j) * 33 + c4];
                s[j] = fmaf(kv.x, mv.x, fmaf(kv.y, mv.y,
                        fmaf(kv.z, mv.z, fmaf(kv.w, mv.w, s[j]))));
            }
        }
    }
    __syncthreads();
#pragma unroll
    for (int j = 0; j < 13; j++)
        if (j < cnt) lg[row * 52 + m0 + j] = s[j];
    __syncthreads();

    if (t < 32) {
        float mx = -1e30f;
        for (int m = 0; m < 50; m++) mx = fmaxf(mx, lg[t * 52 + m]);
        float sum = 0.f;
        for (int m = 0; m < 50; m++) sum += __expf(lg[t * 52 + m] - mx);
        float inv = 1.f / sum;
        size_t ob = (size_t)(bi * 32 + t) * 50;
        for (int m = 0; m < 50; m++)
            Wout[ob + m] = __expf(lg[t * 52 + m] - mx) * inv;
    }
}

// ---------------------------------------------------------------------------
// Scan: grid (4 d-chunks, 64 batches), 128 threads. Lane group-of-4:
// d = dc*32 + (t>>2), mq = t&3 owns 12-13 of the 50 Mv rows in registers.
// w staged in smem (uniform LDS). E/A prefetched 8 steps deep in registers
// (block-unrolled circular buffer) so the LDG round-trip is off the
// per-step critical path. r_t closed by 2 shfl_xor (off recurrence).
// ---------------------------------------------------------------------------
__global__ __launch_bounds__(128) void scan_kernel(
    const float* __restrict__ Wm, const float* __restrict__ E,
    const float* __restrict__ Aa, const float* __restrict__ Mv0,
    float* __restrict__ R)
{
    __shared__ float ws[200 * 50];    // 40 KB

    const int dc = blockIdx.x;
    const int b  = blockIdx.y;
    const int t  = threadIdx.x;
    const int mq = t & 3;
    const int d  = dc * 32 + (t >> 2);
    const int m0  = (mq < 2) ? mq * 13 : 26 + (mq - 2) * 12;
    const int cnt = (mq < 2) ? 13 : 12;

    {
        const float4* src = reinterpret_cast<const float4*>(Wm + (size_t)b * 10000);
        float4* dst = reinterpret_cast<float4*>(ws);
        for (int i = t; i < 2500; i += 128) dst[i] = src[i];
    }

    float mv[13];
#pragma unroll
    for (int i = 0; i < 13; ++i)
        if (i < cnt) mv[i] = Mv0[(m0 + i) * 128 + d];

    const size_t rowbase = (size_t)b * 200;
    const float* Ep = E  + rowbase * 128 + d;
    const float* Ap = Aa + rowbase * 128 + d;
    float*       Rp = R  + rowbase * 128 + d;

    // prime 8-deep E/A register pipeline (issued before the barrier so the
    // loads overlap the w staging drain)
    float eb[8], ab[8];
#pragma unroll
    for (int u = 0; u < 8; ++u) {
        eb[u] = Ep[(size_t)u * 128];
        ab[u] = Ap[(size_t)u * 128];
    }
    __syncthreads();

#pragma unroll 1
    for (int blk = 0; blk < 200; blk += 8) {
#pragma unroll
        for (int u = 0; u < 8; ++u) {
            const int tt = blk + u;
            float ed = eb[u];
            float ad = ab[u];
            // refill this slot for step tt+8 (consumed 8 steps from now)
            if (blk + 8 < 200) {
                eb[u] = Ep[(size_t)(tt + 8) * 128];
                ab[u] = Ap[(size_t)(tt + 8) * 128];
            }

            const float* wrow = ws + tt * 50;
            float ac0 = 0.f, ac1 = 0.f;
#pragma unroll
            for (int i = 0; i < 13; ++i) {
                if (i < cnt) {
                    float wm = wrow[m0 + i];
                    float mvm = mv[i];
                    if (i & 1) ac1 = fmaf(wm, mvm, ac1);
                    else       ac0 = fmaf(wm, mvm, ac0);
                    mv[i] = fmaf(wm, fmaf(-mvm, ed, ad), mvm);
                }
            }
            float partial = ac0 + ac1;
            partial += __shfl_xor_sync(0xffffffffu, partial, 1);
            partial += __shfl_xor_sync(0xffffffffu, partial, 2);
            if (mq == 0) Rp[(size_t)tt * 128] = partial;
        }
    }
}

// ---------------------------------------------------------------------------
extern "C" void kernel_launch(void* const* d_in, const int* in_sizes, int n_in,
                              void* d_out, int out_size)
{
    const int*   q     = (const int*)d_in[0];
    const int*   r     = (const int*)d_in[1];
    // d_in[2] = diff (unused)
    const float* k_emb = (const float*)d_in[3];
    const float* v_emb = (const float*)d_in[4];
    const float* W1 = (const float*)d_in[5];
    const float* b1 = (const float*)d_in[6];
    const float* W2 = (const float*)d_in[7];
    const float* b2 = (const float*)d_in[8];
    const float* Mk  = (const float*)d_in[9];
    const float* Mv0 = (const float*)d_in[10];
    const float* We = (const float*)d_in[11];
    const float* be = (const float*)d_in[12];
    const float* Wa = (const float*)d_in[13];
    const float* ba = (const float*)d_in[14];
    const float* Wf = (const float*)d_in[15];
    const float* bf = (const float*)d_in[16];
    const float* Wp = (const float*)d_in[17];
    const float* bp = (const float*)d_in[18];
    float* out = (float*)d_out;

    float *pk, *pv, *pe, *pa, *pr, *pw;
    cudaGetSymbolAddress((void**)&pk, g_k);
    cudaGetSymbolAddress((void**)&pv, g_v);
    cudaGetSymbolAddress((void**)&pe, g_e);
    cudaGetSymbolAddress((void**)&pa, g_a);
    cudaGetSymbolAddress((void**)&pr, g_reads);
    cudaGetSymbolAddress((void**)&pw, g_w);

    kv_kernel<<<dim3(2, 100, 2), 128>>>(k_emb, v_emb, q, r, W1, b1, W2, b2, pk, pv);
    wsoftmax_kernel<<<400, 128>>>(pk, Mk, pw);
    ea_kernel<<<dim3(2, 100, 2), 128>>>(pv, We, be, Wa, ba, pe, pa);
    scan_kernel<<<dim3(4, 64), 128>>>(pw, pe, pa, Mv0, pr);
    head_kernel<<<200, 128>>>(pr, pk, Wf, bf, Wp, bp, out);
}

// round 15
// speedup vs baseline: 1.8393x; 1.5268x over previous
#include <cuda_runtime.h>
#include <cuda_bf16.h>
#include <math.h>
#include <stdint.h>

// ---------------------------------------------------------------------------
// DKVMN: B=64, L=200, D=128, M=50, FIX=512. Rows = 12800.
//   kv_kernel (tf32 mma): k = k_emb[q]@W1+b1 ; v = v_emb[q+1e4r]@W2+b2
//   wsoftmax : w = softmax(k@Mk^T)  (compact pitch-50)
//   ea_kernel (tf32 mma): e = sigmoid(v@We+be) ; a = tanh(v@Wa+ba)
//   scan : group-of-4 m split, w in smem, E/A 8-deep register prefetch.
//   head : p = sigmoid(tanh([reads|k]@Wf+bf)@Wp+bp)   (fp32 SIMT)
// ---------------------------------------------------------------------------

#define NROWS 12800

__device__ float g_k[NROWS * 128];
__device__ float g_v[NROWS * 128];
__device__ float g_e[NROWS * 128];
__device__ float g_a[NROWS * 128];
__device__ float g_reads[NROWS * 128];
__device__ float g_w[NROWS * 50];   // compact pitch 50

__device__ __forceinline__ float fast_tanh(float x) {
    float y;
    asm("tanh.approx.f32 %0, %1;" : "=f"(y) : "f"(x));
    return y;
}
__device__ __forceinline__ float fast_sig(float x) {
    return 0.5f * fast_tanh(0.5f * x) + 0.5f;
}
__device__ __forceinline__ uint32_t f2tf32(float x) {
    uint32_t y;
    asm("cvt.rna.tf32.f32 %0, %1;" : "=r"(y) : "f"(x));
    return y;
}
__device__ __forceinline__ void mma_tf32(
    float& c0, float& c1, float& c2, float& c3,
    uint32_t a0, uint32_t a1, uint32_t a2, uint32_t a3,
    uint32_t b0, uint32_t b1)
{
    asm volatile(
        "mma.sync.aligned.m16n8k8.row.col.f32.tf32.tf32.f32 "
        "{%0,%1,%2,%3}, {%4,%5,%6,%7}, {%8,%9}, {%0,%1,%2,%3};\n"
        : "+f"(c0), "+f"(c1), "+f"(c2), "+f"(c3)
        : "r"(a0), "r"(a1), "r"(a2), "r"(a3), "r"(b0), "r"(b1));
}

// ---------------------------------------------------------------------------
// tf32 tensor-core 64x128 mainloop. 128 threads (4 warps). BK=16, dbuf.
// Warp w owns cols [w*32, w*32+32) = 4 n8-tiles, all 64 rows = 4 m16-tiles.
// As[64][20] (tf32 bits, pitch 20 conflict-free), Bs[16][136].
// aptr[0]/aptr[1]: global row base ptrs for rows (t>>2) and (t>>2)+32.
// ---------------------------------------------------------------------------
template <int NT>
__device__ __forceinline__ void mm_tc64x128(
    const float* const (&aptr)[2], const float* __restrict__ Wb,
    float (&acc)[4][4][4],
    uint32_t (*As)[64][20], uint32_t (*Bs)[16][136], int t)
{
    const int lslot = t & 3;
    const int lrow  = t >> 2;     // 0..31
    const int lane  = t & 31;
    const int wid   = t >> 5;

    float4 ar[2], br[4];
    auto ldA = [&](int kt) {
        ar[0] = *reinterpret_cast<const float4*>(aptr[0] + kt * 16 + lslot * 4);
        ar[1] = *reinterpret_cast<const float4*>(aptr[1] + kt * 16 + lslot * 4);
    };
    auto ldB = [&](int kt) {
#pragma unroll
        for (int u = 0; u < 4; ++u) {
            int e = t + u * 128;
            int rr = e >> 5, cb = e & 31;
            br[u] = *reinterpret_cast<const float4*>(Wb + (size_t)(kt * 16 + rr) * 128 + cb * 4);
        }
    };
    auto stAB = [&](int buf) {
        uint4 v0 = make_uint4(f2tf32(ar[0].x), f2tf32(ar[0].y), f2tf32(ar[0].z), f2tf32(ar[0].w));
        uint4 v1 = make_uint4(f2tf32(ar[1].x), f2tf32(ar[1].y), f2tf32(ar[1].z), f2tf32(ar[1].w));
        *reinterpret_cast<uint4*>(&As[buf][lrow][lslot * 4])      = v0;
        *reinterpret_cast<uint4*>(&As[buf][lrow + 32][lslot * 4]) = v1;
#pragma unroll
        for (int u = 0; u < 4; ++u) {
            int e = t + u * 128;
            int rr = e >> 5, cb = e & 31;
            uint4 w = make_uint4(f2tf32(br[u].x), f2tf32(br[u].y), f2tf32(br[u].z), f2tf32(br[u].w));
            *reinterpret_cast<uint4*>(&Bs[buf][rr][cb * 4]) = w;
        }
    };

    ldA(0); ldB(0); stAB(0);
    __syncthreads();

#pragma unroll 1
    for (int kt = 0; kt < NT; ++kt) {
        const int cur = kt & 1, nxt = cur ^ 1;
        if (kt + 1 < NT) { ldA(kt + 1); ldB(kt + 1); }
#pragma unroll
        for (int ks = 0; ks < 2; ++ks) {
            const int kk = ks * 8;
            uint32_t bfr[4][2];
#pragma unroll
            for (int nt = 0; nt < 4; ++nt) {
                int col = wid * 32 + nt * 8 + (lane >> 2);
                bfr[nt][0] = Bs[cur][kk + (lane & 3)][col];
                bfr[nt][1] = Bs[cur][kk + (lane & 3) + 4][col];
            }
#pragma unroll
            for (int mt = 0; mt < 4; ++mt) {
                int row = mt * 16 + (lane >> 2);
                uint32_t a0 = As[cur][row][kk + (lane & 3)];
                uint32_t a1 = As[cur][row + 8][kk + (lane & 3)];
                uint32_t a2 = As[cur][row][kk + (lane & 3) + 4];
                uint32_t a3 = As[cur][row + 8][kk + (lane & 3) + 4];
#pragma unroll
                for (int nt = 0; nt < 4; ++nt)
                    mma_tf32(acc[mt][nt][0], acc[mt][nt][1], acc[mt][nt][2], acc[mt][nt][3],
                             a0, a1, a2, a3, bfr[nt][0], bfr[nt][1]);
            }
        }
        if (kt + 1 < NT) stAB(nxt);
        __syncthreads();
    }
}

// ---------------------------------------------------------------------------
// kv_kernel: grid (200, 2). y=0: k path; y=1: v path. K=512 gather GEMM (tf32).
// ---------------------------------------------------------------------------
__global__ __launch_bounds__(128) void kv_kernel(
    const float* __restrict__ k_emb, const float* __restrict__ v_emb,
    const int* __restrict__ qi, const int* __restrict__ ri,
    const float* __restrict__ W1, const float* __restrict__ b1,
    const float* __restrict__ W2, const float* __restrict__ b2,
    float* __restrict__ gk, float* __restrict__ gv)
{
    __shared__ uint32_t As[2][64][20];
    __shared__ uint32_t Bs[2][16][136];

    const int t  = threadIdx.x;
    const int mb = blockIdx.x;
    const int z  = blockIdx.y;
    const int lane = t & 31, wid = t >> 5;

    const float* emb  = z ? v_emb : k_emb;
    const float* W    = z ? W2 : W1;
    const float* bias = z ? b2 : b1;
    float*       C    = z ? gv : gk;

    const float* aptr[2];
    {
        int r0 = mb * 64 + (t >> 2);
        size_t arow0 = (size_t)qi[r0];
        size_t arow1 = (size_t)qi[r0 + 32];
        if (z) {
            arow0 += (size_t)10000 * (size_t)ri[r0];
            arow1 += (size_t)10000 * (size_t)ri[r0 + 32];
        }
        aptr[0] = emb + arow0 * 512;
        aptr[1] = emb + arow1 * 512;
    }

    float acc[4][4][4];
#pragma unroll
    for (int a = 0; a < 4; ++a)
#pragma unroll
        for (int b = 0; b < 4; ++b)
#pragma unroll
            for (int c = 0; c < 4; ++c) acc[a][b][c] = 0.f;

    mm_tc64x128<32>(aptr, W, acc, As, Bs, t);

#pragma unroll
    for (int mt = 0; mt < 4; ++mt) {
#pragma unroll
        for (int nt = 0; nt < 4; ++nt) {
            int col = wid * 32 + nt * 8 + (lane & 3) * 2;
            size_t row0 = (size_t)(mb * 64 + mt * 16 + (lane >> 2));
            float b0 = bias[col], b1v = bias[col + 1];
            float2 v0 = make_float2(acc[mt][nt][0] + b0, acc[mt][nt][1] + b1v);
            float2 v1 = make_float2(acc[mt][nt][2] + b0, acc[mt][nt][3] + b1v);
            *reinterpret_cast<float2*>(C + row0 * 128 + col)       = v0;
            *reinterpret_cast<float2*>(C + (row0 + 8) * 128 + col) = v1;
        }
    }
}

// ---------------------------------------------------------------------------
// ea_kernel: grid (200, 2). y=0: e = sigmoid(v@We+be); y=1: a = tanh(v@Wa+ba)
// K=128 direct GEMM (tf32).
// ---------------------------------------------------------------------------
__global__ __launch_bounds__(128) void ea_kernel(
    const float* __restrict__ V,
    const float* __restrict__ We, const float* __restrict__ be,
    const float* __restrict__ Wa, const float* __restrict__ ba,
    float* __restrict__ ge, float* __restrict__ ga)
{
    __shared__ uint32_t As[2][64][20];
    __shared__ uint32_t Bs[2][16][136];

    const int t  = threadIdx.x;
    const int mb = blockIdx.x;
    const int z  = blockIdx.y;
    const int lane = t & 31, wid = t >> 5;

    const float* W    = z ? Wa : We;
    const float* bias = z ? ba : be;
    float*       C    = z ? ga : ge;

    const float* aptr[2];
    {
        int r0 = mb * 64 + (t >> 2);
        aptr[0] = V + (size_t)r0 * 128;
        aptr[1] = V + (size_t)(r0 + 32) * 128;
    }

    float acc[4][4][4];
#pragma unroll
    for (int a = 0; a < 4; ++a)
#pragma unroll
        for (int b = 0; b < 4; ++b)
#pragma unroll
            for (int c = 0; c < 4; ++c) acc[a][b][c] = 0.f;

    mm_tc64x128<8>(aptr, W, acc, As, Bs, t);

#pragma unroll
    for (int mt = 0; mt < 4; ++mt) {
#pragma unroll
        for (int nt = 0; nt < 4; ++nt) {
            int col = wid * 32 + nt * 8 + (lane & 3) * 2;
            size_t row0 = (size_t)(mb * 64 + mt * 16 + (lane >> 2));
            float b0 = bias[col], b1v = bias[col + 1];
            float o0 = acc[mt][nt][0] + b0, o1 = acc[mt][nt][1] + b1v;
            float o2 = acc[mt][nt][2] + b0, o3 = acc[mt][nt][3] + b1v;
            if (z) { o0 = fast_tanh(o0); o1 = fast_tanh(o1); o2 = fast_tanh(o2); o3 = fast_tanh(o3); }
            else   { o0 = fast_sig(o0);  o1 = fast_sig(o1);  o2 = fast_sig(o2);  o3 = fast_sig(o3); }
            *reinterpret_cast<float2*>(C + row0 * 128 + col)       = make_float2(o0, o1);
            *reinterpret_cast<float2*>(C + (row0 + 8) * 128 + col) = make_float2(o2, o3);
        }
    }
}

// ---------------------------------------------------------------------------
// head: 64x128 tile, 128 threads, 8x8 per thread, K=256 ([reads|k] concat).
// ---------------------------------------------------------------------------
__global__ __launch_bounds__(128) void head_kernel(
    const float* __restrict__ reads, const float* __restrict__ k,
    const float* __restrict__ Wf, const float* __restrict__ bf,
    const float* __restrict__ Wp, const float* __restrict__ bp,
    float* __restrict__ out)
{
    __shared__ float As[2][16][68];
    __shared__ float Bs[2][16][132];
    __shared__ float pbuf[64][17];

    const int t  = threadIdx.x;
    const int mb = blockIdx.x;
    const int cx = t & 15;
    const int ry = t >> 4;
    const int lrow = t >> 1;
    const int c4b  = (t & 1) * 2;

    const float* aR = reads + (size_t)(mb * 64 + lrow) * 128;
    const float* aK = k     + (size_t)(mb * 64 + lrow) * 128;

    float4 ar[2], br[4];
    auto ldA = [&](int kt) {
#pragma unroll
        for (int u = 0; u < 2; ++u) {
            const float* base = (kt < 8) ? (aR + kt * 16) : (aK + (kt - 8) * 16);
            ar[u] = *reinterpret_cast<const float4*>(base + (c4b + u) * 4);
        }
    };
    auto ldB = [&](int kt) {
#pragma unroll
        for (int u = 0; u < 4; ++u) {
            int e = t + u * 128;
            int rr = e >> 5, cb = e & 31;
            br[u] = *reinterpret_cast<const float4*>(Wf + (size_t)(kt * 16 + rr) * 128 + cb * 4);
        }
    };
    auto stAB = [&](int buf) {
#pragma unroll
        for (int u = 0; u < 2; ++u) {
            int kkb = (c4b + u) * 4;
            As[buf][kkb + 0][lrow] = ar[u].x;
            As[buf][kkb + 1][lrow] = ar[u].y;
            As[buf][kkb + 2][lrow] = ar[u].z;
            As[buf][kkb + 3][lrow] = ar[u].w;
        }
#pragma unroll
        for (int u = 0; u < 4; ++u) {
            int e = t + u * 128;
            int rr = e >> 5, cb = e & 31;
            *reinterpret_cast<float4*>(&Bs[buf][rr][cb * 4]) = br[u];
        }
    };

    float acc[8][8];
#pragma unroll
    for (int i = 0; i < 8; i++)
#pragma unroll
        for (int j = 0; j < 8; j++) acc[i][j] = 0.f;

    ldA(0); ldB(0); stAB(0);
    __syncthreads();

#pragma unroll 1
    for (int kt = 0; kt < 16; ++kt) {
        const int cur = kt & 1, nxt = cur ^ 1;
        if (kt + 1 < 16) { ldA(kt + 1); ldB(kt + 1); }
#pragma unroll
        for (int kk = 0; kk < 16; ++kk) {
            float4 a0 = *reinterpret_cast<const float4*>(&As[cur][kk][ry * 8]);
            float4 a1 = *reinterpret_cast<const float4*>(&As[cur][kk][ry * 8 + 4]);
            float4 b0 = *reinterpret_cast<const float4*>(&Bs[cur][kk][cx * 8]);
            float4 b1 = *reinterpret_cast<const float4*>(&Bs[cur][kk][cx * 8 + 4]);
            float aa[8] = {a0.x, a0.y, a0.z, a0.w, a1.x, a1.y, a1.z, a1.w};
            float bb[8] = {b0.x, b0.y, b0.z, b0.w, b1.x, b1.y, b1.z, b1.w};
#pragma unroll
            for (int i = 0; i < 8; ++i)
#pragma unroll
                for (int j = 0; j < 8; ++j)
                    acc[i][j] = fmaf(aa[i], bb[j], acc[i][j]);
        }
        if (kt + 1 < 16) stAB(nxt);
        __syncthreads();
    }

#pragma unroll
    for (int i = 0; i < 8; ++i) {
        float pac = 0.f;
#pragma unroll
        for (int j = 0; j < 8; ++j) {
            int c = cx * 8 + j;
            float f = fast_tanh(acc[i][j] + bf[c]);
            pac = fmaf(f, Wp[c], pac);
        }
        pbuf[ry * 8 + i][cx] = pac;
    }
    __syncthreads();
    if (t < 64) {
        float s = bp[0];
#pragma unroll
        for (int x = 0; x < 16; ++x) s += pbuf[t][x];
        out[mb * 64 + t] = 1.f / (1.f + __expf(-s));
    }
}

// ---------------------------------------------------------------------------
// w = softmax(k @ Mk^T) : 32 rows/CTA, 128 threads. COMPACT pitch-50 output.
// ---------------------------------------------------------------------------
__global__ __launch_bounds__(128) void wsoftmax_kernel(
    const float* __restrict__ K, const float* __restrict__ Mk,
    float* __restrict__ Wout)
{
    __shared__ float sm_k[32 * 132];
    __shared__ float sm_m[50 * 132];
    float4* kt4 = reinterpret_cast<float4*>(sm_k);
    float4* mk4 = reinterpret_cast<float4*>(sm_m);
    float*  lg  = sm_k;

    const int t  = threadIdx.x;
    const int bi = blockIdx.x;

    for (int e = t; e < 32 * 32; e += 128) {
        int rw = e >> 5, c4 = e & 31;
        kt4[rw * 33 + c4] =
            *reinterpret_cast<const float4*>(K + ((size_t)(bi * 32 + rw)) * 128 + c4 * 4);
    }
    for (int e = t; e < 50 * 32; e += 128) {
        int m = e >> 5, c4 = e & 31;
        mk4[m * 33 + c4] = *reinterpret_cast<const float4*>(Mk + (size_t)m * 128 + c4 * 4);
    }
    __syncthreads();

    const int row = t >> 2;
    const int mg  = t & 3;
    const int m0  = (mg < 2) ? mg * 13 : 26 + (mg - 2) * 12;
    const int cnt = (mg < 2) ? 13 : 12;

    float s[13];
#pragma unroll
    for (int j = 0; j < 13; j++) s[j] = 0.f;

    for (int c4 = 0; c4 < 32; ++c4) {
        float4 kv = kt4[row * 33 + c4];
#pragma unroll
        for (int j = 0; j < 13; j++) {
            if (j < cnt) {
                float4 mv = mk4[(m0 + j) * 33 + c4];
                s[j] = fmaf(kv.x, mv.x, fmaf(kv.y, mv.y,
                        fmaf(kv.z, mv.z, fmaf(kv.w, mv.w, s[j]))));
            }
        }
    }
    __syncthreads();
#pragma unroll
    for (int j = 0; j < 13; j++)
        if (j < cnt) lg[row * 52 + m0 + j] = s[j];
    __syncthreads();

    if (t < 32) {
        float mx = -1e30f;
        for (int m = 0; m < 50; m++) mx = fmaxf(mx, lg[t * 52 + m]);
        float sum = 0.f;
        for (int m = 0; m < 50; m++) sum += __expf(lg[t * 52 + m] - mx);
        float inv = 1.f / sum;
        size_t ob = (size_t)(bi * 32 + t) * 50;
        for (int m = 0; m < 50; m++)
            Wout[ob + m] = __expf(lg[t * 52 + m] - mx) * inv;
    }
}

// ---------------------------------------------------------------------------
// Scan (R14): grid (4,64), 128 thr; group-of-4 m split, w in smem,
// E/A 8-deep register prefetch, shfl r-reduction, no barriers in loop.
// ---------------------------------------------------------------------------
__global__ __launch_bounds__(128) void scan_kernel(
    const float* __restrict__ Wm, const float* __restrict__ E,
    const float* __restrict__ Aa, const float* __restrict__ Mv0,
    float* __restrict__ R)
{
    __shared__ float ws[200 * 50];    // 40 KB

    const int dc = blockIdx.x;
    const int b  = blockIdx.y;
    const int t  = threadIdx.x;
    const int mq = t & 3;
    const int d  = dc * 32 + (t >> 2);
    const int m0  = (mq < 2) ? mq * 13 : 26 + (mq - 2) * 12;
    const int cnt = (mq < 2) ? 13 : 12;

    {
        const float4* src = reinterpret_cast<const float4*>(Wm + (size_t)b * 10000);
        float4* dst = reinterpret_cast<float4*>(ws);
        for (int i = t; i < 2500; i += 128) dst[i] = src[i];
    }

    float mv[13];
#pragma unroll
    for (int i = 0; i < 13; ++i)
        if (i < cnt) mv[i] = Mv0[(m0 + i) * 128 + d];

    const size_t rowbase = (size_t)b * 200;
    const float* Ep = E  + rowbase * 128 + d;
    const float* Ap = Aa + rowbase * 128 + d;
    float*       Rp = R  + rowbase * 128 + d;

    float eb[8], ab[8];
#pragma unroll
    for (int u = 0; u < 8; ++u) {
        eb[u] = Ep[(size_t)u * 128];
        ab[u] = Ap[(size_t)u * 128];
    }
    __syncthreads();

#pragma unroll 1
    for (int blk = 0; blk < 200; blk += 8) {
#pragma unroll
        for (int u = 0; u < 8; ++u) {
            const int tt = blk + u;
            float ed = eb[u];
            float ad = ab[u];
            if (blk + 8 < 200) {
                eb[u] = Ep[(size_t)(tt + 8) * 128];
                ab[u] = Ap[(size_t)(tt + 8) * 128];
            }

            const float* wrow = ws + tt * 50;
            float ac0 = 0.f, ac1 = 0.f;
#pragma unroll
            for (int i = 0; i < 13; ++i) {
                if (i < cnt) {
                    float wm = wrow[m0 + i];
                    float mvm = mv[i];
                    if (i & 1) ac1 = fmaf(wm, mvm, ac1);
                    else       ac0 = fmaf(wm, mvm, ac0);
                    mv[i] = fmaf(wm, fmaf(-mvm, ed, ad), mvm);
                }
            }
            float partial = ac0 + ac1;
            partial += __shfl_xor_sync(0xffffffffu, partial, 1);
            partial += __shfl_xor_sync(0xffffffffu, partial, 2);
            if (mq == 0) Rp[(size_t)tt * 128] = partial;
        }
    }
}

// ---------------------------------------------------------------------------
extern "C" void kernel_launch(void* const* d_in, const int* in_sizes, int n_in,
                              void* d_out, int out_size)
{
    const int*   q     = (const int*)d_in[0];
    const int*   r     = (const int*)d_in[1];
    // d_in[2] = diff (unused)
    const float* k_emb = (const float*)d_in[3];
    const float* v_emb = (const float*)d_in[4];
    const float* W1 = (const float*)d_in[5];
    const float* b1 = (const float*)d_in[6];
    const float* W2 = (const float*)d_in[7];
    const float* b2 = (const float*)d_in[8];
    const float* Mk  = (const float*)d_in[9];
    const float* Mv0 = (const float*)d_in[10];
    const float* We = (const float*)d_in[11];
    const float* be = (const float*)d_in[12];
    const float* Wa = (const float*)d_in[13];
    const float* ba = (const float*)d_in[14];
    const float* Wf = (const float*)d_in[15];
    const float* bf = (const float*)d_in[16];
    const float* Wp = (const float*)d_in[17];
    const float* bp = (const float*)d_in[18];
    float* out = (float*)d_out;

    float *pk, *pv, *pe, *pa, *pr, *pw;
    cudaGetSymbolAddress((void**)&pk, g_k);
    cudaGetSymbolAddress((void**)&pv, g_v);
    cudaGetSymbolAddress((void**)&pe, g_e);
    cudaGetSymbolAddress((void**)&pa, g_a);
    cudaGetSymbolAddress((void**)&pr, g_reads);
    cudaGetSymbolAddress((void**)&pw, g_w);

    kv_kernel<<<dim3(200, 2), 128>>>(k_emb, v_emb, q, r, W1, b1, W2, b2, pk, pv);
    wsoftmax_kernel<<<400, 128>>>(pk, Mk, pw);
    ea_kernel<<<dim3(200, 2), 128>>>(pv, We, be, Wa, ba, pe, pa);
    scan_kernel<<<dim3(4, 64), 128>>>(pw, pe, pa, Mv0, pr);
    head_kernel<<<200, 128>>>(pr, pk, Wf, bf, Wp, bp, out);
}

// round 17
// speedup vs baseline: 2.1448x; 1.1661x over previous
#include <cuda_runtime.h>
#include <cuda_bf16.h>
#include <math.h>
#include <stdint.h>

// ---------------------------------------------------------------------------
// DKVMN: B=64, L=200, D=128, M=50, FIX=512. Rows = 12800.
//   kv_kernel (tf32 mma): k = k_emb[q]@W1+b1 ; v = v_emb[q+1e4r]@W2+b2
//   wsoftmax : w = softmax(k@Mk^T)  (compact pitch-50)
//   ea_kernel (tf32 mma): e = sigmoid(v@We+be) ; a = tanh(v@Wa+ba)
//   scan : group-of-4 m split, w in smem, E/A 8-deep register prefetch.
//   head (tf32 mma, K=256 concat): p = sigmoid(tanh([reads|k]@Wf+bf)@Wp+bp)
// ---------------------------------------------------------------------------

#define NROWS 12800

__device__ float g_k[NROWS * 128];
__device__ float g_v[NROWS * 128];
__device__ float g_e[NROWS * 128];
__device__ float g_a[NROWS * 128];
__device__ float g_reads[NROWS * 128];
__device__ float g_w[NROWS * 50];   // compact pitch 50

__device__ __forceinline__ float fast_tanh(float x) {
    float y;
    asm("tanh.approx.f32 %0, %1;" : "=f"(y) : "f"(x));
    return y;
}
__device__ __forceinline__ float fast_sig(float x) {
    return 0.5f * fast_tanh(0.5f * x) + 0.5f;
}
__device__ __forceinline__ uint32_t f2tf32(float x) {
    uint32_t y;
    asm("cvt.rna.tf32.f32 %0, %1;" : "=r"(y) : "f"(x));
    return y;
}
__device__ __forceinline__ void mma_tf32(
    float& c0, float& c1, float& c2, float& c3,
    uint32_t a0, uint32_t a1, uint32_t a2, uint32_t a3,
    uint32_t b0, uint32_t b1)
{
    asm volatile(
        "mma.sync.aligned.m16n8k8.row.col.f32.tf32.tf32.f32 "
        "{%0,%1,%2,%3}, {%4,%5,%6,%7}, {%8,%9}, {%0,%1,%2,%3};\n"
        : "+f"(c0), "+f"(c1), "+f"(c2), "+f"(c3)
        : "r"(a0), "r"(a1), "r"(a2), "r"(a3), "r"(b0), "r"(b1));
}

// ---------------------------------------------------------------------------
// tf32 tensor-core 64x128 mainloop. 128 threads (4 warps). BK=16, dbuf.
// Warp w owns cols [w*32, w*32+32) = 4 n8-tiles, all 64 rows = 4 m16-tiles.
// A rows: kt < SPLIT from aA[·], kt >= SPLIT from aB[·] (concat support).
// ---------------------------------------------------------------------------
template <int NT, int SPLIT>
__device__ __forceinline__ void mm_tc64x128(
    const float* const (&aA)[2], const float* const (&aB)[2],
    const float* __restrict__ Wb, float (&acc)[4][4][4],
    uint32_t (*As)[64][20], uint32_t (*Bs)[16][136], int t)
{
    const int lslot = t & 3;
    const int lrow  = t >> 2;     // 0..31
    const int lane  = t & 31;
    const int wid   = t >> 5;

    float4 ar[2], br[4];
    auto ldA = [&](int kt) {
        const float* b0 = (kt < SPLIT) ? aA[0] : aB[0];
        const float* b1 = (kt < SPLIT) ? aA[1] : aB[1];
        int off = (kt < SPLIT) ? kt * 16 : (kt - SPLIT) * 16;
        ar[0] = *reinterpret_cast<const float4*>(b0 + off + lslot * 4);
        ar[1] = *reinterpret_cast<const float4*>(b1 + off + lslot * 4);
    };
    auto ldB = [&](int kt) {
#pragma unroll
        for (int u = 0; u < 4; ++u) {
            int e = t + u * 128;
            int rr = e >> 5, cb = e & 31;
            br[u] = *reinterpret_cast<const float4*>(Wb + (size_t)(kt * 16 + rr) * 128 + cb * 4);
        }
    };
    auto stAB = [&](int buf) {
        uint4 v0 = make_uint4(f2tf32(ar[0].x), f2tf32(ar[0].y), f2tf32(ar[0].z), f2tf32(ar[0].w));
        uint4 v1 = make_uint4(f2tf32(ar[1].x), f2tf32(ar[1].y), f2tf32(ar[1].z), f2tf32(ar[1].w));
        *reinterpret_cast<uint4*>(&As[buf][lrow][lslot * 4])      = v0;
        *reinterpret_cast<uint4*>(&As[buf][lrow + 32][lslot * 4]) = v1;
#pragma unroll
        for (int u = 0; u < 4; ++u) {
            int e = t + u * 128;
            int rr = e >> 5, cb = e & 31;
            uint4 w = make_uint4(f2tf32(br[u].x), f2tf32(br[u].y), f2tf32(br[u].z), f2tf32(br[u].w));
            *reinterpret_cast<uint4*>(&Bs[buf][rr][cb * 4]) = w;
        }
    };

    ldA(0); ldB(0); stAB(0);
    __syncthreads();

#pragma unroll 1
    for (int kt = 0; kt < NT; ++kt) {
        const int cur = kt & 1, nxt = cur ^ 1;
        if (kt + 1 < NT) { ldA(kt + 1); ldB(kt + 1); }
#pragma unroll
        for (int ks = 0; ks < 2; ++ks) {
            const int kk = ks * 8;
            uint32_t bfr[4][2];
#pragma unroll
            for (int nt = 0; nt < 4; ++nt) {
                int col = wid * 32 + nt * 8 + (lane >> 2);
                bfr[nt][0] = Bs[cur][kk + (lane & 3)][col];
                bfr[nt][1] = Bs[cur][kk + (lane & 3) + 4][col];
            }
#pragma unroll
            for (int mt = 0; mt < 4; ++mt) {
                int row = mt * 16 + (lane >> 2);
                uint32_t a0 = As[cur][row][kk + (lane & 3)];
                uint32_t a1 = As[cur][row + 8][kk + (lane & 3)];
                uint32_t a2 = As[cur][row][kk + (lane & 3) + 4];
                uint32_t a3 = As[cur][row + 8][kk + (lane & 3) + 4];
#pragma unroll
                for (int nt = 0; nt < 4; ++nt)
                    mma_tf32(acc[mt][nt][0], acc[mt][nt][1], acc[mt][nt][2], acc[mt][nt][3],
                             a0, a1, a2, a3, bfr[nt][0], bfr[nt][1]);
            }
        }
        if (kt + 1 < NT) stAB(nxt);
        __syncthreads();
    }
}

// ---------------------------------------------------------------------------
// kv_kernel: grid (200, 2). y=0: k path; y=1: v path. K=512 gather GEMM (tf32).
// ---------------------------------------------------------------------------
__global__ __launch_bounds__(128) void kv_kernel(
    const float* __restrict__ k_emb, const float* __restrict__ v_emb,
    const int* __restrict__ qi, const int* __restrict__ ri,
    const float* __restrict__ W1, const float* __restrict__ b1,
    const float* __restrict__ W2, const float* __restrict__ b2,
    float* __restrict__ gk, float* __restrict__ gv)
{
    __shared__ uint32_t As[2][64][20];
    __shared__ uint32_t Bs[2][16][136];

    const int t  = threadIdx.x;
    const int mb = blockIdx.x;
    const int z  = blockIdx.y;
    const int lane = t & 31, wid = t >> 5;

    const float* emb  = z ? v_emb : k_emb;
    const float* W    = z ? W2 : W1;
    const float* bias = z ? b2 : b1;
    float*       C    = z ? gv : gk;

    const float* aptr[2];
    {
        int r0 = mb * 64 + (t >> 2);
        size_t arow0 = (size_t)qi[r0];
        size_t arow1 = (size_t)qi[r0 + 32];
        if (z) {
            arow0 += (size_t)10000 * (size_t)ri[r0];
            arow1 += (size_t)10000 * (size_t)ri[r0 + 32];
        }
        aptr[0] = emb + arow0 * 512;
        aptr[1] = emb + arow1 * 512;
    }

    float acc[4][4][4];
#pragma unroll
    for (int a = 0; a < 4; ++a)
#pragma unroll
        for (int b = 0; b < 4; ++b)
#pragma unroll
            for (int c = 0; c < 4; ++c) acc[a][b][c] = 0.f;

    mm_tc64x128<32, 32>(aptr, aptr, W, acc, As, Bs, t);

#pragma unroll
    for (int mt = 0; mt < 4; ++mt) {
#pragma unroll
        for (int nt = 0; nt < 4; ++nt) {
            int col = wid * 32 + nt * 8 + (lane & 3) * 2;
            size_t row0 = (size_t)(mb * 64 + mt * 16 + (lane >> 2));
            float b0 = bias[col], b1v = bias[col + 1];
            float2 v0 = make_float2(acc[mt][nt][0] + b0, acc[mt][nt][1] + b1v);
            float2 v1 = make_float2(acc[mt][nt][2] + b0, acc[mt][nt][3] + b1v);
            *reinterpret_cast<float2*>(C + row0 * 128 + col)       = v0;
            *reinterpret_cast<float2*>(C + (row0 + 8) * 128 + col) = v1;
        }
    }
}

// ---------------------------------------------------------------------------
// ea_kernel: grid (200, 2). y=0: e = sigmoid(v@We+be); y=1: a = tanh(v@Wa+ba)
// ---------------------------------------------------------------------------
__global__ __launch_bounds__(128) void ea_kernel(
    const float* __restrict__ V,
    const float* __restrict__ We, const float* __restrict__ be,
    const float* __restrict__ Wa, const float* __restrict__ ba,
    float* __restrict__ ge, float* __restrict__ ga)
{
    __shared__ uint32_t As[2][64][20];
    __shared__ uint32_t Bs[2][16][136];

    const int t  = threadIdx.x;
    const int mb = blockIdx.x;
    const int z  = blockIdx.y;
    const int lane = t & 31, wid = t >> 5;

    const float* W    = z ? Wa : We;
    const float* bias = z ? ba : be;
    float*       C    = z ? ga : ge;

    const float* aptr[2];
    {
        int r0 = mb * 64 + (t >> 2);
        aptr[0] = V + (size_t)r0 * 128;
        aptr[1] = V + (size_t)(r0 + 32) * 128;
    }

    float acc[4][4][4];
#pragma unroll
    for (int a = 0; a < 4; ++a)
#pragma unroll
        for (int b = 0; b < 4; ++b)
#pragma unroll
            for (int c = 0; c < 4; ++c) acc[a][b][c] = 0.f;

    mm_tc64x128<8, 8>(aptr, aptr, W, acc, As, Bs, t);

#pragma unroll
    for (int mt = 0; mt < 4; ++mt) {
#pragma unroll
        for (int nt = 0; nt < 4; ++nt) {
            int col = wid * 32 + nt * 8 + (lane & 3) * 2;
            size_t row0 = (size_t)(mb * 64 + mt * 16 + (lane >> 2));
            float b0 = bias[col], b1v = bias[col + 1];
            float o0 = acc[mt][nt][0] + b0, o1 = acc[mt][nt][1] + b1v;
            float o2 = acc[mt][nt][2] + b0, o3 = acc[mt][nt][3] + b1v;
            if (z) { o0 = fast_tanh(o0); o1 = fast_tanh(o1); o2 = fast_tanh(o2); o3 = fast_tanh(o3); }
            else   { o0 = fast_sig(o0);  o1 = fast_sig(o1);  o2 = fast_sig(o2);  o3 = fast_sig(o3); }
            *reinterpret_cast<float2*>(C + row0 * 128 + col)       = make_float2(o0, o1);
            *reinterpret_cast<float2*>(C + (row0 + 8) * 128 + col) = make_float2(o2, o3);
        }
    }
}

// ---------------------------------------------------------------------------
// head: tf32 mma, 64 rows/CTA, K=256 ([reads|k] concat via SPLIT=8).
// Fused p = sigmoid(tanh(f+bf) . Wp + bp) in fragment space.
// ---------------------------------------------------------------------------
__global__ __launch_bounds__(128) void head_kernel(
    const float* __restrict__ reads, const float* __restrict__ k,
    const float* __restrict__ Wf, const float* __restrict__ bf,
    const float* __restrict__ Wp, const float* __restrict__ bp,
    float* __restrict__ out)
{
    __shared__ uint32_t As[2][64][20];
    __shared__ uint32_t Bs[2][16][136];
    __shared__ float pbuf[64][17];

    const int t  = threadIdx.x;
    const int mb = blockIdx.x;
    const int lane = t & 31, wid = t >> 5;

    const float* aR[2];
    const float* aK[2];
    {
        int r0 = mb * 64 + (t >> 2);
        aR[0] = reads + (size_t)r0 * 128;
        aR[1] = reads + (size_t)(r0 + 32) * 128;
        aK[0] = k + (size_t)r0 * 128;
        aK[1] = k + (size_t)(r0 + 32) * 128;
    }

    float acc[4][4][4];
#pragma unroll
    for (int a = 0; a < 4; ++a)
#pragma unroll
        for (int b = 0; b < 4; ++b)
#pragma unroll
            for (int c = 0; c < 4; ++c) acc[a][b][c] = 0.f;

    mm_tc64x128<16, 8>(aR, aK, Wf, acc, As, Bs, t);

    // fused epilogue: per-thread partial p over its 8 cols, 2 row-halves x 4 mt
#pragma unroll
    for (int mt = 0; mt < 4; ++mt) {
        float p0 = 0.f, p1 = 0.f;
#pragma unroll
        for (int nt = 0; nt < 4; ++nt) {
            int col = wid * 32 + nt * 8 + (lane & 3) * 2;
            float bf0 = bf[col], bf1 = bf[col + 1];
            float wp0 = Wp[col], wp1 = Wp[col + 1];
            p0 = fmaf(fast_tanh(acc[mt][nt][0] + bf0), wp0, p0);
            p0 = fmaf(fast_tanh(acc[mt][nt][1] + bf1), wp1, p0);
            p1 = fmaf(fast_tanh(acc[mt][nt][2] + bf0), wp0, p1);
            p1 = fmaf(fast_tanh(acc[mt][nt][3] + bf1), wp1, p1);
        }
        int row = mt * 16 + (lane >> 2);
        int slot = wid * 4 + (lane & 3);
        pbuf[row][slot]     = p0;
        pbuf[row + 8][slot] = p1;
    }
    __syncthreads();
    if (t < 64) {
        float s = bp[0];
#pragma unroll
        for (int x = 0; x < 16; ++x) s += pbuf[t][x];
        out[mb * 64 + t] = 1.f / (1.f + __expf(-s));
    }
}

// ---------------------------------------------------------------------------
// w = softmax(k @ Mk^T) : 32 rows/CTA, 128 threads. COMPACT pitch-50 output.
// ---------------------------------------------------------------------------
__global__ __launch_bounds__(128) void wsoftmax_kernel(
    const float* __restrict__ K, const float* __restrict__ Mk,
    float* __restrict__ Wout)
{
    __shared__ float sm_k[32 * 132];
    __shared__ float sm_m[50 * 132];
    float4* kt4 = reinterpret_cast<float4*>(sm_k);
    float4* mk4 = reinterpret_cast<float4*>(sm_m);
    float*  lg  = sm_k;

    const int t  = threadIdx.x;
    const int bi = blockIdx.x;

    for (int e = t; e < 32 * 32; e += 128) {
        int rw = e >> 5, c4 = e & 31;
        kt4[rw * 33 + c4] =
            *reinterpret_cast<const float4*>(K + ((size_t)(bi * 32 + rw)) * 128 + c4 * 4);
    }
    for (int e = t; e < 50 * 32; e += 128) {
        int m = e >> 5, c4 = e & 31;
        mk4[m * 33 + c4] = *reinterpret_cast<const float4*>(Mk + (size_t)m * 128 + c4 * 4);
    }
    __syncthreads();

    const int row = t >> 2;
    const int mg  = t & 3;
    const int m0  = (mg < 2) ? mg * 13 : 26 + (mg - 2) * 12;
    const int cnt = (mg < 2) ? 13 : 12;

    float s[13];
#pragma unroll
    for (int j = 0; j < 13; j++) s[j] = 0.f;

    for (int c4 = 0; c4 < 32; ++c4) {
        float4 kv = kt4[row * 33 + c4];
#pragma unroll
        for (int j = 0; j < 13; j++) {
            if (j < cnt) {
                float4 mv = mk4[(m0 + j) * 33 + c4];
                s[j] = fmaf(kv.x, mv.x, fmaf(kv.y, mv.y,
                        fmaf(kv.z, mv.z, fmaf(kv.w, mv.w, s[j]))));
            }
        }
    }
    __syncthreads();
#pragma unroll
    for (int j = 0; j < 13; j++)
        if (j < cnt) lg[row * 52 + m0 + j] = s[j];
    __syncthreads();

    if (t < 32) {
        float mx = -1e30f;
        for (int m = 0; m < 50; m++) mx = fmaxf(mx, lg[t * 52 + m]);
        float sum = 0.f;
        for (int m = 0; m < 50; m++) sum += __expf(lg[t * 52 + m] - mx);
        float inv = 1.f / sum;
        size_t ob = (size_t)(bi * 32 + t) * 50;
        for (int m = 0; m < 50; m++)
            Wout[ob + m] = __expf(lg[t * 52 + m] - mx) * inv;
    }
}

// ---------------------------------------------------------------------------
// Scan (R14): grid (4,64), 128 thr; group-of-4 m split, w in smem,
// E/A 8-deep register prefetch, shfl r-reduction, no barriers in loop.
// ---------------------------------------------------------------------------
__global__ __launch_bounds__(128) void scan_kernel(
    const float* __restrict__ Wm, const float* __restrict__ E,
    const float* __restrict__ Aa, const float* __restrict__ Mv0,
    float* __restrict__ R)
{
    __shared__ float ws[200 * 50];    // 40 KB

    const int dc = blockIdx.x;
    const int b  = blockIdx.y;
    const int t  = threadIdx.x;
    const int mq = t & 3;
    const int d  = dc * 32 + (t >> 2);
    const int m0  = (mq < 2) ? mq * 13 : 26 + (mq - 2) * 12;
    const int cnt = (mq < 2) ? 13 : 12;

    {
        const float4* src = reinterpret_cast<const float4*>(Wm + (size_t)b * 10000);
        float4* dst = reinterpret_cast<float4*>(ws);
        for (int i = t; i < 2500; i += 128) dst[i] = src[i];
    }

    float mv[13];
#pragma unroll
    for (int i = 0; i < 13; ++i)
        if (i < cnt) mv[i] = Mv0[(m0 + i) * 128 + d];

    const size_t rowbase = (size_t)b * 200;
    const float* Ep = E  + rowbase * 128 + d;
    const float* Ap = Aa + rowbase * 128 + d;
    float*       Rp = R  + rowbase * 128 + d;

    float eb[8], ab[8];
#pragma unroll
    for (int u = 0; u < 8; ++u) {
        eb[u] = Ep[(size_t)u * 128];
        ab[u] = Ap[(size_t)u * 128];
    }
    __syncthreads();

#pragma unroll 1
    for (int blk = 0; blk < 200; blk += 8) {
#pragma unroll
        for (int u = 0; u < 8; ++u) {
            const int tt = blk + u;
            float ed = eb[u];
            float ad = ab[u];
            if (blk + 8 < 200) {
                eb[u] = Ep[(size_t)(tt + 8) * 128];
                ab[u] = Ap[(size_t)(tt + 8) * 128];
            }

            const float* wrow = ws + tt * 50;
            float ac0 = 0.f, ac1 = 0.f;
#pragma unroll
            for (int i = 0; i < 13; ++i) {
                if (i < cnt) {
                    float wm = wrow[m0 + i];
                    float mvm = mv[i];
                    if (i & 1) ac1 = fmaf(wm, mvm, ac1);
                    else       ac0 = fmaf(wm, mvm, ac0);
                    mv[i] = fmaf(wm, fmaf(-mvm, ed, ad), mvm);
                }
            }
            float partial = ac0 + ac1;
            partial += __shfl_xor_sync(0xffffffffu, partial, 1);
            partial += __shfl_xor_sync(0xffffffffu, partial, 2);
            if (mq == 0) Rp[(size_t)tt * 128] = partial;
        }
    }
}

// ---------------------------------------------------------------------------
extern "C" void kernel_launch(void* const* d_in, const int* in_sizes, int n_in,
                              void* d_out, int out_size)
{
    const int*   q     = (const int*)d_in[0];
    const int*   r     = (const int*)d_in[1];
    // d_in[2] = diff (unused)
    const float* k_emb = (const float*)d_in[3];
    const float* v_emb = (const float*)d_in[4];
    const float* W1 = (const float*)d_in[5];
    const float* b1 = (const float*)d_in[6];
    const float* W2 = (const float*)d_in[7];
    const float* b2 = (const float*)d_in[8];
    const float* Mk  = (const float*)d_in[9];
    const float* Mv0 = (const float*)d_in[10];
    const float* We = (const float*)d_in[11];
    const float* be = (const float*)d_in[12];
    const float* Wa = (const float*)d_in[13];
    const float* ba = (const float*)d_in[14];
    const float* Wf = (const float*)d_in[15];
    const float* bf = (const float*)d_in[16];
    const float* Wp = (const float*)d_in[17];
    const float* bp = (const float*)d_in[18];
    float* out = (float*)d_out;

    float *pk, *pv, *pe, *pa, *pr, *pw;
    cudaGetSymbolAddress((void**)&pk, g_k);
    cudaGetSymbolAddress((void**)&pv, g_v);
    cudaGetSymbolAddress((void**)&pe, g_e);
    cudaGetSymbolAddress((void**)&pa, g_a);
    cudaGetSymbolAddress((void**)&pr, g_reads);
    cudaGetSymbolAddress((void**)&pw, g_w);

    kv_kernel<<<dim3(200, 2), 128>>>(k_emb, v_emb, q, r, W1, b1, W2, b2, pk, pv);
    wsoftmax_kernel<<<400, 128>>>(pk, Mk, pw);
    ea_kernel<<<dim3(200, 2), 128>>>(pv, We, be, Wa, ba, pe, pa);
    scan_kernel<<<dim3(4, 64), 128>>>(pw, pe, pa, Mv0, pr);
    head_kernel<<<200, 128>>>(pr, pk, Wf, bf, Wp, bp, out);
}